// round 1
// baseline (speedup 1.0000x reference)
#include <cuda_runtime.h>
#include <math.h>

// Problem constants
constexpr int BATCH = 8;
constexpr int SQ    = 2048;
constexpr int SKV   = 2048;
constexpr int DIN   = 1024;
constexpr int DEMB  = 512;
constexpr int DOUT  = 512;

constexpr long PROJ_ELEMS = (long)BATCH * SQ * DOUT;   // 8388608
constexpr long ATT_ELEMS  = (long)BATCH * SQ * SKV;    // 33554432

// Scratch (allocation-free rule: device globals)
__device__ float g_q  [BATCH * SQ * DEMB];   // q = x@Wq + bq
__device__ float g_sum[BATCH * SQ * DEMB];   // values + q residual

// ---------------------------------------------------------------------------
// Tiled SGEMM: C[M,N] = A[M,K] @ B + epilogue
//   BT=true : B stored [N,K] row-major (B^T GEMM, used for Q@K^T)
//   BT=false: B stored [K,N] row-major
//   EPI=0: C += bias[col]        (aux = bias vector)
//   EPI=1: C *= scale
//   EPI=2: C += aux[row*N+col]   (residual matrix, batched via sAux)
// Tiles: 128x128, BK=16, 256 threads, 8x8 per-thread microtile.
// All dims in this problem are multiples of 128/16 -> no bounds checks.
// ---------------------------------------------------------------------------
template <int EPI, bool BT>
__global__ void __launch_bounds__(256)
sgemm128(const float* __restrict__ A, const float* __restrict__ Bm,
         float* __restrict__ C, int M, int N, int K,
         long sA, long sB, long sC,
         const float* __restrict__ aux, long sAux, float scale)
{
    A  += (long)blockIdx.z * sA;
    Bm += (long)blockIdx.z * sB;
    C  += (long)blockIdx.z * sC;
    const float* auxp = aux;
    if (EPI == 2) auxp += (long)blockIdx.z * sAux;

    const int m0 = blockIdx.y * 128;
    const int n0 = blockIdx.x * 128;

    __shared__ __align__(16) float As[16][132];
    __shared__ __align__(16) float Bs[16][132];

    const int tid = threadIdx.x;
    const int ty = tid >> 4;       // 0..15
    const int tx = tid & 15;       // 0..15

    // A / BT loads: 128 rows x 16 cols, 2 float4 per thread
    const int ar = tid >> 2;          // 0..63
    const int ac = (tid & 3) * 4;     // 0,4,8,12
    // !BT loads: 16 rows x 128 cols
    const int br = tid >> 5;          // 0..7
    const int bc = (tid & 31) * 4;    // 0..124

    float acc[8][8];
#pragma unroll
    for (int i = 0; i < 8; i++)
#pragma unroll
        for (int j = 0; j < 8; j++) acc[i][j] = 0.0f;

    for (int k0 = 0; k0 < K; k0 += 16) {
        // Load A tile (store transposed: As[k][m])
#pragma unroll
        for (int h = 0; h < 2; h++) {
            int r = ar + h * 64;
            float4 va = *reinterpret_cast<const float4*>(
                &A[(long)(m0 + r) * K + k0 + ac]);
            As[ac + 0][r] = va.x; As[ac + 1][r] = va.y;
            As[ac + 2][r] = va.z; As[ac + 3][r] = va.w;
        }
        if (BT) {
#pragma unroll
            for (int h = 0; h < 2; h++) {
                int r = ar + h * 64;
                float4 vb = *reinterpret_cast<const float4*>(
                    &Bm[(long)(n0 + r) * K + k0 + ac]);
                Bs[ac + 0][r] = vb.x; Bs[ac + 1][r] = vb.y;
                Bs[ac + 2][r] = vb.z; Bs[ac + 3][r] = vb.w;
            }
        } else {
#pragma unroll
            for (int h = 0; h < 2; h++) {
                int r = br + h * 8;
                float4 vb = *reinterpret_cast<const float4*>(
                    &Bm[(long)(k0 + r) * N + n0 + bc]);
                *reinterpret_cast<float4*>(&Bs[r][bc]) = vb;
            }
        }
        __syncthreads();

#pragma unroll
        for (int kk = 0; kk < 16; kk++) {
            float a[8], b[8];
            *reinterpret_cast<float4*>(&a[0]) = *reinterpret_cast<const float4*>(&As[kk][ty * 8]);
            *reinterpret_cast<float4*>(&a[4]) = *reinterpret_cast<const float4*>(&As[kk][ty * 8 + 4]);
            *reinterpret_cast<float4*>(&b[0]) = *reinterpret_cast<const float4*>(&Bs[kk][tx * 8]);
            *reinterpret_cast<float4*>(&b[4]) = *reinterpret_cast<const float4*>(&Bs[kk][tx * 8 + 4]);
#pragma unroll
            for (int i = 0; i < 8; i++)
#pragma unroll
                for (int j = 0; j < 8; j++)
                    acc[i][j] += a[i] * b[j];
        }
        __syncthreads();
    }

    // Epilogue + store
#pragma unroll
    for (int i = 0; i < 8; i++) {
        const long row = m0 + ty * 8 + i;
#pragma unroll
        for (int j = 0; j < 8; j++) {
            const int col = n0 + tx * 8 + j;
            float v = acc[i][j];
            if (EPI == 0)      v += aux[col];
            else if (EPI == 1) v *= scale;
            else               v += auxp[row * (long)N + col];
            acc[i][j] = v;
        }
        *reinterpret_cast<float4*>(&C[row * (long)N + n0 + tx * 8])     = *reinterpret_cast<float4*>(&acc[i][0]);
        *reinterpret_cast<float4*>(&C[row * (long)N + n0 + tx * 8 + 4]) = *reinterpret_cast<float4*>(&acc[i][4]);
    }
}

// ---------------------------------------------------------------------------
// In-place row softmax over 2048 columns. One block (256 threads) per row.
// ---------------------------------------------------------------------------
__global__ void __launch_bounds__(256)
softmax_rows(float* __restrict__ att)
{
    const long row = blockIdx.x;
    float* p = att + row * (long)SKV;
    const int t = threadIdx.x;

    float v[8];
    float m = -INFINITY;
#pragma unroll
    for (int i = 0; i < 8; i++) {
        v[i] = p[t + i * 256];
        m = fmaxf(m, v[i]);
    }

    __shared__ float red[256];
    red[t] = m;
    __syncthreads();
#pragma unroll
    for (int s = 128; s > 0; s >>= 1) {
        if (t < s) red[t] = fmaxf(red[t], red[t + s]);
        __syncthreads();
    }
    m = red[0];
    __syncthreads();

    float sum = 0.0f;
#pragma unroll
    for (int i = 0; i < 8; i++) {
        v[i] = expf(v[i] - m);
        sum += v[i];
    }
    red[t] = sum;
    __syncthreads();
#pragma unroll
    for (int s = 128; s > 0; s >>= 1) {
        if (t < s) red[t] += red[t + s];
        __syncthreads();
    }
    const float inv = 1.0f / red[0];
#pragma unroll
    for (int i = 0; i < 8; i++)
        p[t + i * 256] = v[i] * inv;
}

// ---------------------------------------------------------------------------
extern "C" void kernel_launch(void* const* d_in, const int* in_sizes, int n_in,
                              void* d_out, int out_size)
{
    const float* x  = (const float*)d_in[0];   // [B, SQ, DIN]
    const float* en = (const float*)d_in[1];   // [B, SKV, DEMB]  (K and V)
    const float* Wq = (const float*)d_in[2];   // [DIN, DEMB]
    const float* bq = (const float*)d_in[3];   // [DEMB]
    const float* Wf = (const float*)d_in[4];   // [DEMB, DOUT]
    const float* bf = (const float*)d_in[5];   // [DOUT]

    float* out  = (float*)d_out;
    float* proj = out;                 // [B, SQ, DOUT]
    float* att  = out + PROJ_ELEMS;    // [B, SQ, SKV]

    float* qptr = nullptr;
    float* sumptr = nullptr;
    cudaGetSymbolAddress((void**)&qptr,   g_q);
    cudaGetSymbolAddress((void**)&sumptr, g_sum);

    const float scale = 0.044194173824159216f;  // 1/sqrt(512)

    // 1) q = x @ Wq + bq   -> g_q  (M=16384, N=512, K=1024)
    sgemm128<0, false><<<dim3(DEMB / 128, (BATCH * SQ) / 128, 1), 256>>>(
        x, Wq, qptr, BATCH * SQ, DEMB, DIN,
        0, 0, 0, bq, 0, 0.0f);

    // 2) S = q @ K^T * scale -> att  (per batch: M=2048, N=2048, K=512)
    sgemm128<1, true><<<dim3(SKV / 128, SQ / 128, BATCH), 256>>>(
        qptr, en, att, SQ, SKV, DEMB,
        (long)SQ * DEMB, (long)SKV * DEMB, (long)SQ * SKV,
        nullptr, 0, scale);

    // 3) softmax rows in-place
    softmax_rows<<<BATCH * SQ, 256>>>(att);

    // 4) sum = A @ V + q -> g_sum  (per batch: M=2048, N=512, K=2048)
    sgemm128<2, false><<<dim3(DEMB / 128, SQ / 128, BATCH), 256>>>(
        att, en, sumptr, SQ, DEMB, SKV,
        (long)SQ * SKV, (long)SKV * DEMB, (long)SQ * DEMB,
        qptr, (long)SQ * DEMB, 0.0f);

    // 5) proj = sum @ Wf + bf -> out  (M=16384, N=512, K=512)
    sgemm128<0, false><<<dim3(DOUT / 128, (BATCH * SQ) / 128, 1), 256>>>(
        sumptr, Wf, proj, BATCH * SQ, DOUT, DEMB,
        0, 0, 0, bf, 0, 0.0f);

    (void)in_sizes; (void)n_in; (void)out_size;
}

// round 4
// speedup vs baseline: 2.6331x; 2.6331x over previous
#include <cuda_runtime.h>
#include <cuda_bf16.h>
#include <math.h>
#include <stdint.h>

// ---------------------------------------------------------------------------
// Problem constants
// ---------------------------------------------------------------------------
constexpr int BATCH = 8;
constexpr int SQ    = 2048;
constexpr int SKV   = 2048;
constexpr int DIN   = 1024;
constexpr int DEMB  = 512;
constexpr int DOUT  = 512;

constexpr long PROJ_ELEMS = (long)BATCH * SQ * DOUT;

// ---------------------------------------------------------------------------
// Scratch (device globals; no allocation allowed)
// ---------------------------------------------------------------------------
__device__ __align__(16) __nv_bfloat16 g_xhi [(long)BATCH * SQ * DIN];
__device__ __align__(16) __nv_bfloat16 g_xlo [(long)BATCH * SQ * DIN];
__device__ __align__(16) __nv_bfloat16 g_wqT_hi[DEMB * DIN];
__device__ __align__(16) __nv_bfloat16 g_wqT_lo[DEMB * DIN];
__device__ __align__(16) __nv_bfloat16 g_enhi[(long)BATCH * SKV * DEMB];
__device__ __align__(16) __nv_bfloat16 g_enlo[(long)BATCH * SKV * DEMB];
__device__ __align__(16) __nv_bfloat16 g_enT_hi[(long)BATCH * DEMB * SKV];
__device__ __align__(16) __nv_bfloat16 g_enT_lo[(long)BATCH * DEMB * SKV];
__device__ __align__(16) __nv_bfloat16 g_wfT_hi[DOUT * DEMB];
__device__ __align__(16) __nv_bfloat16 g_wfT_lo[DOUT * DEMB];
__device__ __align__(16) float         g_q   [(long)BATCH * SQ * DEMB];
__device__ __align__(16) __nv_bfloat16 g_qhi [(long)BATCH * SQ * DEMB];
__device__ __align__(16) __nv_bfloat16 g_qlo [(long)BATCH * SQ * DEMB];
__device__ __align__(16) __nv_bfloat16 g_atthi[(long)BATCH * SQ * SKV];
__device__ __align__(16) __nv_bfloat16 g_attlo[(long)BATCH * SQ * SKV];
__device__ __align__(16) __nv_bfloat16 g_sumhi[(long)BATCH * SQ * DEMB];
__device__ __align__(16) __nv_bfloat16 g_sumlo[(long)BATCH * SQ * DEMB];

// ---------------------------------------------------------------------------
// PTX helpers (sm_80-compatible path only: mma.sync / ldmatrix / cp.async)
// ---------------------------------------------------------------------------
__device__ __forceinline__ uint32_t smem_u32(const void* p) {
    uint32_t a;
    asm("{ .reg .u64 t; cvta.to.shared.u64 t, %1; cvt.u32.u64 %0, t; }" : "=r"(a) : "l"(p));
    return a;
}

#define CP_ASYNC16(dst, src) \
    asm volatile("cp.async.cg.shared.global [%0], [%1], 16;" :: "r"(dst), "l"(src))
#define CP_COMMIT()  asm volatile("cp.async.commit_group;" ::: "memory")
#define CP_WAIT0()   asm volatile("cp.async.wait_group 0;" ::: "memory")
#define CP_WAIT1()   asm volatile("cp.async.wait_group 1;" ::: "memory")

#define LDSM_X4(r0, r1, r2, r3, addr) \
    asm volatile("ldmatrix.sync.aligned.m8n8.x4.shared.b16 {%0,%1,%2,%3}, [%4];" \
                 : "=r"(r0), "=r"(r1), "=r"(r2), "=r"(r3) : "r"(addr))

#define MMA_BF16(d, a, b0, b1) \
    asm volatile("mma.sync.aligned.m16n8k16.row.col.f32.bf16.bf16.f32 " \
                 "{%0,%1,%2,%3}, {%4,%5,%6,%7}, {%8,%9}, {%0,%1,%2,%3};" \
                 : "+f"((d)[0]), "+f"((d)[1]), "+f"((d)[2]), "+f"((d)[3]) \
                 : "r"((a)[0]), "r"((a)[1]), "r"((a)[2]), "r"((a)[3]), \
                   "r"(b0), "r"(b1))

// ---------------------------------------------------------------------------
// bf16 split helpers
// ---------------------------------------------------------------------------
__device__ __forceinline__ void split_bf16(float v, __nv_bfloat16& hi, __nv_bfloat16& lo) {
    hi = __float2bfloat16(v);
    lo = __float2bfloat16(v - __bfloat162float(hi));
}
__device__ __forceinline__ uint32_t pack2(__nv_bfloat16 a, __nv_bfloat16 b) {
    return (uint32_t)__bfloat16_as_ushort(a) | ((uint32_t)__bfloat16_as_ushort(b) << 16);
}

// ---------------------------------------------------------------------------
// Split kernels
// ---------------------------------------------------------------------------
__global__ void __launch_bounds__(256)
split_plain(const float* __restrict__ src, __nv_bfloat16* __restrict__ hi,
            __nv_bfloat16* __restrict__ lo, long n4)
{
    long i = (long)blockIdx.x * 256 + threadIdx.x;
    if (i >= n4) return;
    float4 v = reinterpret_cast<const float4*>(src)[i];
    __nv_bfloat16 h0,l0,h1,l1,h2,l2,h3,l3;
    split_bf16(v.x,h0,l0); split_bf16(v.y,h1,l1);
    split_bf16(v.z,h2,l2); split_bf16(v.w,h3,l3);
    reinterpret_cast<uint2*>(hi)[i] = make_uint2(pack2(h0,h1), pack2(h2,h3));
    reinterpret_cast<uint2*>(lo)[i] = make_uint2(pack2(l0,l1), pack2(l2,l3));
}

// transpose + split: src [R,C] fp32 -> dst [C,R] bf16 hi/lo. block (32,8)
__global__ void __launch_bounds__(256)
split_T(const float* __restrict__ src, __nv_bfloat16* __restrict__ hiT,
        __nv_bfloat16* __restrict__ loT, int R, int C, long sSrc, long sDst)
{
    src += (long)blockIdx.z * sSrc;
    hiT += (long)blockIdx.z * sDst;
    loT += (long)blockIdx.z * sDst;
    __shared__ float t[32][33];
    const int c0 = blockIdx.x * 32;
    const int r0 = blockIdx.y * 32;
    const int tx = threadIdx.x, ty = threadIdx.y;
#pragma unroll
    for (int j = 0; j < 4; j++) {
        int r = r0 + ty + j * 8;
        t[ty + j * 8][tx] = src[(long)r * C + c0 + tx];
    }
    __syncthreads();
#pragma unroll
    for (int j = 0; j < 4; j++) {
        int c = c0 + ty + j * 8;
        float v = t[tx][ty + j * 8];
        __nv_bfloat16 h, l;
        split_bf16(v, h, l);
        hiT[(long)c * R + r0 + tx] = h;
        loT[(long)c * R + r0 + tx] = l;
    }
}

// ---------------------------------------------------------------------------
// bf16x3 HMMA GEMM: C[M,N] = A[M,K] @ B[N,K]^T (+epilogue)
// A,B given as (hi,lo) bf16 K-major. CTA tile 128x128, BK=32, cp.async
// double buffer, 8 warps of 64x32, mma.sync m16n8k16.
// SMEM rows padded to 80B -> conflict-free ldmatrix.
// MODE bits: 1=bias, 2=scale, 4=residual, 8=write fp32, 16=write split
// ---------------------------------------------------------------------------
constexpr int ROWB   = 80;            // padded row bytes (32 bf16 = 64B data)
constexpr int TILEB  = 128 * ROWB;    // 10240 B per tile
constexpr int SMEM_BYTES = 8 * TILEB; // 2 stages x 4 tiles = 81920 B

template <int MODE>
__global__ void __launch_bounds__(256, 2)
mma_gemm(const __nv_bfloat16* __restrict__ Ahi, const __nv_bfloat16* __restrict__ Alo,
         const __nv_bfloat16* __restrict__ Bhi, const __nv_bfloat16* __restrict__ Blo,
         float* __restrict__ Cf, __nv_bfloat16* __restrict__ Chi, __nv_bfloat16* __restrict__ Clo,
         const float* __restrict__ aux,
         int M, int N, int K,
         long sA, long sB, long sC, long sAux, float scale)
{
    constexpr bool HAS_BIAS  = (MODE & 1)  != 0;
    constexpr bool HAS_SCALE = (MODE & 2)  != 0;
    constexpr bool HAS_RES   = (MODE & 4)  != 0;
    constexpr bool WR_F32    = (MODE & 8)  != 0;
    constexpr bool WR_SPLIT  = (MODE & 16) != 0;

    extern __shared__ __align__(128) char dsm[];
    const uint32_t sbase = smem_u32(dsm);
    #define TILE(s, t) (sbase + ((s) * 4 + (t)) * TILEB)

    const int tid  = threadIdx.x;
    const int wid  = tid >> 5;
    const int lane = tid & 31;

    const long z = blockIdx.z;
    Ahi += z * sA;  Alo += z * sA;
    Bhi += z * sB;  Blo += z * sB;
    const long cOff = z * sC;

    const int m0 = blockIdx.y * 128;
    const int n0 = blockIdx.x * 128;

    // loader: 4 tiles x 128 rows x 32 bf16 (64B) per stage
    const int lrow = tid >> 2;           // 0..63 (x2 halves)
    const int lkg  = tid & 3;            // 16B group in row
    auto load_chunk = [&](int s, int k0) {
        const __nv_bfloat16* gp[4] = {
            Ahi + (long)m0 * K + k0, Alo + (long)m0 * K + k0,
            Bhi + (long)n0 * K + k0, Blo + (long)n0 * K + k0 };
#pragma unroll
        for (int t = 0; t < 4; t++) {
            const __nv_bfloat16* g = gp[t];
            const uint32_t st = TILE(s, t);
#pragma unroll
            for (int h = 0; h < 2; h++) {
                int row = lrow + h * 64;
                CP_ASYNC16(st + row * ROWB + lkg * 16,
                           g + (long)row * K + lkg * 8);
            }
        }
    };

    float acc[4][4][4];
#pragma unroll
    for (int a = 0; a < 4; a++)
#pragma unroll
        for (int b = 0; b < 4; b++)
#pragma unroll
            for (int c = 0; c < 4; c++) acc[a][b][c] = 0.0f;

    const int nch = K >> 5;

    load_chunk(0, 0);
    CP_COMMIT();

    // warp layout: 2 (m) x 4 (n); warp tile 64x32
    const int m0w = (wid & 1) * 64;
    const int n0w = (wid >> 1) * 32;

    // ldmatrix lane address components
    const int a_r  = lane & 15;          // row within 16
    const int a_h  = lane >> 4;          // k half
    const int b_r  = lane & 7;
    const int b_q  = lane >> 3;          // 0..3: (n-half, k-half)

    for (int i = 0; i < nch; i++) {
        if (i + 1 < nch) {
            load_chunk((i + 1) & 1, (i + 1) * 32);
            CP_COMMIT();
            CP_WAIT1();
        } else {
            CP_WAIT0();
        }
        __syncthreads();

        const int s = i & 1;
        const uint32_t Abh = TILE(s, 0), Abl = TILE(s, 1);
        const uint32_t Bbh = TILE(s, 2), Bbl = TILE(s, 3);

#pragma unroll
        for (int ks = 0; ks < 2; ks++) {
            const int koff = ks * 32;    // bytes (16 bf16)
            uint32_t bh[8], bl[8];
#pragma unroll
            for (int j = 0; j < 2; j++) {
                uint32_t boff = (uint32_t)((n0w + j * 16 + (b_q >> 1) * 8 + b_r) * ROWB
                                           + koff + (b_q & 1) * 16);
                LDSM_X4(bh[j*4+0], bh[j*4+1], bh[j*4+2], bh[j*4+3], Bbh + boff);
                LDSM_X4(bl[j*4+0], bl[j*4+1], bl[j*4+2], bl[j*4+3], Bbl + boff);
            }
#pragma unroll
            for (int mi = 0; mi < 4; mi++) {
                uint32_t aoff = (uint32_t)((m0w + mi * 16 + a_r) * ROWB + koff + a_h * 16);
                uint32_t ahr[4], alr[4];
                LDSM_X4(ahr[0], ahr[1], ahr[2], ahr[3], Abh + aoff);
                LDSM_X4(alr[0], alr[1], alr[2], alr[3], Abl + aoff);
#pragma unroll
                for (int ni = 0; ni < 4; ni++) {
                    MMA_BF16(acc[mi][ni], ahr, bh[ni*2], bh[ni*2+1]);
                    MMA_BF16(acc[mi][ni], ahr, bl[ni*2], bl[ni*2+1]);
                    MMA_BF16(acc[mi][ni], alr, bh[ni*2], bh[ni*2+1]);
                }
            }
        }
        __syncthreads();
    }

    // ---- epilogue ----
    const float* auxp = aux;
    if (HAS_RES) auxp += z * sAux;
    const int crow = lane >> 2;          // 0..7
    const int ccol = (lane & 3) * 2;
#pragma unroll
    for (int mi = 0; mi < 4; mi++) {
#pragma unroll
        for (int rh = 0; rh < 2; rh++) {
            const long row = m0 + m0w + mi * 16 + crow + rh * 8;
#pragma unroll
            for (int ni = 0; ni < 4; ni++) {
                const int col = n0 + n0w + ni * 8 + ccol;
                float v0 = acc[mi][ni][rh * 2];
                float v1 = acc[mi][ni][rh * 2 + 1];
                if (HAS_BIAS)  { v0 += aux[col]; v1 += aux[col + 1]; }
                if (HAS_SCALE) { v0 *= scale; v1 *= scale; }
                if (HAS_RES)   {
                    v0 += auxp[row * (long)N + col];
                    v1 += auxp[row * (long)N + col + 1];
                }
                if (WR_F32)
                    *reinterpret_cast<float2*>(Cf + cOff + row * (long)N + col) =
                        make_float2(v0, v1);
                if (WR_SPLIT) {
                    __nv_bfloat16 h0, l0, h1, l1;
                    split_bf16(v0, h0, l0);
                    split_bf16(v1, h1, l1);
                    *reinterpret_cast<uint32_t*>(Chi + cOff + row * (long)N + col) = pack2(h0, h1);
                    *reinterpret_cast<uint32_t*>(Clo + cOff + row * (long)N + col) = pack2(l0, l1);
                }
            }
        }
    }
    #undef TILE
}

// ---------------------------------------------------------------------------
// Softmax over 2048 cols, in-place fp32, fused bf16 hi/lo split write.
// ---------------------------------------------------------------------------
__global__ void __launch_bounds__(256)
softmax_split(float* __restrict__ att, __nv_bfloat16* __restrict__ hi,
              __nv_bfloat16* __restrict__ lo)
{
    const long row = blockIdx.x;
    float* p = att + row * (long)SKV;
    const int t = threadIdx.x;

    float v[8];
    float m = -INFINITY;
#pragma unroll
    for (int i = 0; i < 8; i++) {
        v[i] = p[t + i * 256];
        m = fmaxf(m, v[i]);
    }
    __shared__ float red[256];
    red[t] = m;
    __syncthreads();
#pragma unroll
    for (int s = 128; s > 0; s >>= 1) {
        if (t < s) red[t] = fmaxf(red[t], red[t + s]);
        __syncthreads();
    }
    m = red[0];
    __syncthreads();
    float sum = 0.0f;
#pragma unroll
    for (int i = 0; i < 8; i++) {
        v[i] = expf(v[i] - m);
        sum += v[i];
    }
    red[t] = sum;
    __syncthreads();
#pragma unroll
    for (int s = 128; s > 0; s >>= 1) {
        if (t < s) red[t] += red[t + s];
        __syncthreads();
    }
    const float inv = 1.0f / red[0];
    __nv_bfloat16* hp = hi + row * (long)SKV;
    __nv_bfloat16* lp = lo + row * (long)SKV;
#pragma unroll
    for (int i = 0; i < 8; i++) {
        float val = v[i] * inv;
        p[t + i * 256] = val;
        __nv_bfloat16 h, l;
        split_bf16(val, h, l);
        hp[t + i * 256] = h;
        lp[t + i * 256] = l;
    }
}

// ---------------------------------------------------------------------------
extern "C" void kernel_launch(void* const* d_in, const int* in_sizes, int n_in,
                              void* d_out, int out_size)
{
    const float* x  = (const float*)d_in[0];
    const float* en = (const float*)d_in[1];
    const float* Wq = (const float*)d_in[2];
    const float* bq = (const float*)d_in[3];
    const float* Wf = (const float*)d_in[4];
    const float* bf = (const float*)d_in[5];

    float* out  = (float*)d_out;
    float* proj = out;
    float* att  = out + PROJ_ELEMS;

    auto sym = [](const void* s) {
        void* p = nullptr;
        cudaGetSymbolAddress(&p, s);
        return p;
    };
    __nv_bfloat16* xhi   = (__nv_bfloat16*)sym(g_xhi);
    __nv_bfloat16* xlo   = (__nv_bfloat16*)sym(g_xlo);
    __nv_bfloat16* wqThi = (__nv_bfloat16*)sym(g_wqT_hi);
    __nv_bfloat16* wqTlo = (__nv_bfloat16*)sym(g_wqT_lo);
    __nv_bfloat16* enhi  = (__nv_bfloat16*)sym(g_enhi);
    __nv_bfloat16* enlo  = (__nv_bfloat16*)sym(g_enlo);
    __nv_bfloat16* enThi = (__nv_bfloat16*)sym(g_enT_hi);
    __nv_bfloat16* enTlo = (__nv_bfloat16*)sym(g_enT_lo);
    __nv_bfloat16* wfThi = (__nv_bfloat16*)sym(g_wfT_hi);
    __nv_bfloat16* wfTlo = (__nv_bfloat16*)sym(g_wfT_lo);
    float*         qf    = (float*)        sym(g_q);
    __nv_bfloat16* qhi   = (__nv_bfloat16*)sym(g_qhi);
    __nv_bfloat16* qlo   = (__nv_bfloat16*)sym(g_qlo);
    __nv_bfloat16* atthi = (__nv_bfloat16*)sym(g_atthi);
    __nv_bfloat16* attlo = (__nv_bfloat16*)sym(g_attlo);
    __nv_bfloat16* sumhi = (__nv_bfloat16*)sym(g_sumhi);
    __nv_bfloat16* sumlo = (__nv_bfloat16*)sym(g_sumlo);

    cudaFuncSetAttribute(mma_gemm<25>, cudaFuncAttributeMaxDynamicSharedMemorySize, SMEM_BYTES);
    cudaFuncSetAttribute(mma_gemm<10>, cudaFuncAttributeMaxDynamicSharedMemorySize, SMEM_BYTES);
    cudaFuncSetAttribute(mma_gemm<20>, cudaFuncAttributeMaxDynamicSharedMemorySize, SMEM_BYTES);
    cudaFuncSetAttribute(mma_gemm<9>,  cudaFuncAttributeMaxDynamicSharedMemorySize, SMEM_BYTES);

    const float scale = 0.044194173824159216f;  // 1/sqrt(512)

    // --- input splits ---
    {
        long n4 = (long)BATCH * SQ * DIN / 4;
        split_plain<<<(unsigned)((n4 + 255) / 256), 256>>>(x, xhi, xlo, n4);
    }
    {
        long n4 = (long)BATCH * SKV * DEMB / 4;
        split_plain<<<(unsigned)((n4 + 255) / 256), 256>>>(en, enhi, enlo, n4);
    }
    split_T<<<dim3(DEMB / 32, SKV / 32, BATCH), dim3(32, 8)>>>(
        en, enThi, enTlo, SKV, DEMB, (long)SKV * DEMB, (long)DEMB * SKV);
    split_T<<<dim3(DEMB / 32, DIN / 32, 1), dim3(32, 8)>>>(
        Wq, wqThi, wqTlo, DIN, DEMB, 0, 0);
    split_T<<<dim3(DOUT / 32, DEMB / 32, 1), dim3(32, 8)>>>(
        Wf, wfThi, wfTlo, DEMB, DOUT, 0, 0);

    // 1) q = x @ WqT^T + bq  (fp32 q + split)   MODE = bias|f32|split
    mma_gemm<25><<<dim3(DEMB / 128, (BATCH * SQ) / 128, 1), 256, SMEM_BYTES>>>(
        xhi, xlo, wqThi, wqTlo, qf, qhi, qlo, bq,
        BATCH * SQ, DEMB, DIN, 0, 0, 0, 0, 0.0f);

    // 2) scores = q @ en^T * scale  (fp32 to att region)  MODE = scale|f32
    mma_gemm<10><<<dim3(SKV / 128, SQ / 128, BATCH), 256, SMEM_BYTES>>>(
        qhi, qlo, enhi, enlo, att, nullptr, nullptr, nullptr,
        SQ, SKV, DEMB,
        (long)SQ * DEMB, (long)SKV * DEMB, (long)SQ * SKV, 0, scale);

    // 3) softmax + split
    softmax_split<<<BATCH * SQ, 256>>>(att, atthi, attlo);

    // 4) sum = att @ enT^T + q  (split only)  MODE = residual|split
    mma_gemm<20><<<dim3(DEMB / 128, SQ / 128, BATCH), 256, SMEM_BYTES>>>(
        atthi, attlo, enThi, enTlo, nullptr, sumhi, sumlo, qf,
        SQ, DEMB, SKV,
        (long)SQ * SKV, (long)DEMB * SKV, (long)SQ * DEMB, (long)SQ * DEMB, 0.0f);

    // 5) proj = sum @ WfT^T + bf  (fp32 out)  MODE = bias|f32
    mma_gemm<9><<<dim3(DOUT / 128, (BATCH * SQ) / 128, 1), 256, SMEM_BYTES>>>(
        sumhi, sumlo, wfThi, wfTlo, proj, nullptr, nullptr, bf,
        BATCH * SQ, DOUT, DEMB, 0, 0, 0, 0, 0.0f);

    (void)in_sizes; (void)n_in; (void)out_size;
}

// round 5
// speedup vs baseline: 3.1579x; 1.1993x over previous
#include <cuda_runtime.h>
#include <cuda_bf16.h>
#include <cuda_fp16.h>
#include <math.h>
#include <stdint.h>

// ---------------------------------------------------------------------------
// Problem constants
// ---------------------------------------------------------------------------
constexpr int BATCH = 8;
constexpr int SQ    = 2048;
constexpr int SKV   = 2048;
constexpr int DIN   = 1024;
constexpr int DEMB  = 512;
constexpr int DOUT  = 512;

constexpr long PROJ_ELEMS = (long)BATCH * SQ * DOUT;

// ---------------------------------------------------------------------------
// Scratch (device globals; no allocation allowed)
// ---------------------------------------------------------------------------
__device__ __align__(16) uint16_t g_xh [(long)BATCH * SQ * DIN];    // fp16 hi
__device__ __align__(16) uint16_t g_xl [(long)BATCH * SQ * DIN];    // fp16 lo
__device__ __align__(16) uint16_t g_wqT[DEMB * DIN];                // fp16 single
__device__ __align__(16) uint16_t g_enhi[(long)BATCH * SKV * DEMB]; // bf16 hi
__device__ __align__(16) uint16_t g_enlo[(long)BATCH * SKV * DEMB]; // bf16 lo
__device__ __align__(16) uint16_t g_enT[(long)BATCH * DEMB * SKV];  // fp16 single, transposed
__device__ __align__(16) uint16_t g_wfT[DOUT * DEMB];               // fp16 single
__device__ __align__(16) float    g_q  [(long)BATCH * SQ * DEMB];   // fp32 (residual)
__device__ __align__(16) uint16_t g_qhi[(long)BATCH * SQ * DEMB];   // bf16 hi
__device__ __align__(16) uint16_t g_qlo[(long)BATCH * SQ * DEMB];   // bf16 lo
__device__ __align__(16) uint16_t g_sumh[(long)BATCH * SQ * DEMB];  // fp16 hi
__device__ __align__(16) uint16_t g_suml[(long)BATCH * SQ * DEMB];  // fp16 lo

// ---------------------------------------------------------------------------
// PTX helpers (sm_80-compatible path: mma.sync / ldmatrix / cp.async)
// ---------------------------------------------------------------------------
__device__ __forceinline__ uint32_t smem_u32(const void* p) {
    uint32_t a;
    asm("{ .reg .u64 t; cvta.to.shared.u64 t, %1; cvt.u32.u64 %0, t; }" : "=r"(a) : "l"(p));
    return a;
}

#define CP_ASYNC16(dst, src) \
    asm volatile("cp.async.cg.shared.global [%0], [%1], 16;" :: "r"(dst), "l"(src))
#define CP_COMMIT()  asm volatile("cp.async.commit_group;" ::: "memory")
#define CP_WAIT0()   asm volatile("cp.async.wait_group 0;" ::: "memory")
#define CP_WAIT1()   asm volatile("cp.async.wait_group 1;" ::: "memory")

#define LDSM_X4(r0, r1, r2, r3, addr) \
    asm volatile("ldmatrix.sync.aligned.m8n8.x4.shared.b16 {%0,%1,%2,%3}, [%4];" \
                 : "=r"(r0), "=r"(r1), "=r"(r2), "=r"(r3) : "r"(addr))

template <bool F16>
__device__ __forceinline__ void mma16(float* d, const uint32_t* a, uint32_t b0, uint32_t b1) {
    if (F16)
        asm volatile("mma.sync.aligned.m16n8k16.row.col.f32.f16.f16.f32 "
                     "{%0,%1,%2,%3}, {%4,%5,%6,%7}, {%8,%9}, {%0,%1,%2,%3};"
                     : "+f"(d[0]), "+f"(d[1]), "+f"(d[2]), "+f"(d[3])
                     : "r"(a[0]), "r"(a[1]), "r"(a[2]), "r"(a[3]), "r"(b0), "r"(b1));
    else
        asm volatile("mma.sync.aligned.m16n8k16.row.col.f32.bf16.bf16.f32 "
                     "{%0,%1,%2,%3}, {%4,%5,%6,%7}, {%8,%9}, {%0,%1,%2,%3};"
                     : "+f"(d[0]), "+f"(d[1]), "+f"(d[2]), "+f"(d[3])
                     : "r"(a[0]), "r"(a[1]), "r"(a[2]), "r"(a[3]), "r"(b0), "r"(b1));
}

// ---------------------------------------------------------------------------
// split helpers
// ---------------------------------------------------------------------------
__device__ __forceinline__ void split_bf(float v, uint16_t& h, uint16_t& l) {
    __nv_bfloat16 hb = __float2bfloat16(v);
    __nv_bfloat16 lb = __float2bfloat16(v - __bfloat162float(hb));
    h = __bfloat16_as_ushort(hb);
    l = __bfloat16_as_ushort(lb);
}
__device__ __forceinline__ void split_h(float v, uint16_t& h, uint16_t& l) {
    __half hh = __float2half_rn(v);
    __half ll = __float2half_rn(v - __half2float(hh));
    h = __half_as_ushort(hh);
    l = __half_as_ushort(ll);
}
__device__ __forceinline__ uint32_t pk(uint16_t a, uint16_t b) {
    return (uint32_t)a | ((uint32_t)b << 16);
}

// ---------------------------------------------------------------------------
// Pre-pass kernels
// ---------------------------------------------------------------------------
// x -> fp16 hi/lo
__global__ void __launch_bounds__(256)
split_plain_f16(const float* __restrict__ src, uint16_t* __restrict__ hi,
                uint16_t* __restrict__ lo, long n4)
{
    long i = (long)blockIdx.x * 256 + threadIdx.x;
    if (i >= n4) return;
    float4 v = reinterpret_cast<const float4*>(src)[i];
    uint16_t h0,l0,h1,l1,h2,l2,h3,l3;
    split_h(v.x,h0,l0); split_h(v.y,h1,l1);
    split_h(v.z,h2,l2); split_h(v.w,h3,l3);
    reinterpret_cast<uint2*>(hi)[i] = make_uint2(pk(h0,h1), pk(h2,h3));
    reinterpret_cast<uint2*>(lo)[i] = make_uint2(pk(l0,l1), pk(l2,l3));
}

// en -> bf16 hi/lo (same layout) + fp16 single transposed [DEMB, SKV]
__global__ void __launch_bounds__(256)
split_en_fused(const float* __restrict__ en, uint16_t* __restrict__ ehi,
               uint16_t* __restrict__ elo, uint16_t* __restrict__ eT)
{
    const long z = blockIdx.z;
    en  += z * (long)SKV * DEMB;
    ehi += z * (long)SKV * DEMB;
    elo += z * (long)SKV * DEMB;
    eT  += z * (long)DEMB * SKV;
    __shared__ float t[32][33];
    const int c0 = blockIdx.x * 32;   // DEMB
    const int r0 = blockIdx.y * 32;   // SKV
    const int tx = threadIdx.x, ty = threadIdx.y;
#pragma unroll
    for (int j = 0; j < 4; j++) {
        int r = r0 + ty + j * 8;
        float v = en[(long)r * DEMB + c0 + tx];
        t[ty + j * 8][tx] = v;
        uint16_t h, l;
        split_bf(v, h, l);
        ehi[(long)r * DEMB + c0 + tx] = h;
        elo[(long)r * DEMB + c0 + tx] = l;
    }
    __syncthreads();
#pragma unroll
    for (int j = 0; j < 4; j++) {
        int c = c0 + ty + j * 8;
        float v = t[tx][ty + j * 8];
        eT[(long)c * SKV + r0 + tx] = __half_as_ushort(__float2half_rn(v));
    }
}

// W [R,C] fp32 -> WT [C,R] fp16 single
__global__ void __launch_bounds__(256)
conv_T_f16(const float* __restrict__ src, uint16_t* __restrict__ dstT, int R, int C)
{
    __shared__ float t[32][33];
    const int c0 = blockIdx.x * 32;
    const int r0 = blockIdx.y * 32;
    const int tx = threadIdx.x, ty = threadIdx.y;
#pragma unroll
    for (int j = 0; j < 4; j++) {
        int r = r0 + ty + j * 8;
        t[ty + j * 8][tx] = src[(long)r * C + c0 + tx];
    }
    __syncthreads();
#pragma unroll
    for (int j = 0; j < 4; j++) {
        int c = c0 + ty + j * 8;
        dstT[(long)c * R + r0 + tx] = __half_as_ushort(__float2half_rn(t[tx][ty + j * 8]));
    }
}

// ---------------------------------------------------------------------------
// Unified HMMA GEMM: C[M,N] = A[M,K] @ B[N,K]^T (+epilogue)
// PASSES=3: bf16x3 (Ah,Al,Bh,Bl tiles); PASSES=2: fp16x2 (Ah,Al,B tiles).
// AF32: A read as fp32 and split to fp16 hi/lo in the loader.
// MODE bits: 1=bias, 2=scale, 4=residual, 8=write fp32,
//            16=write bf16 split, 32=write fp16 split
// ---------------------------------------------------------------------------
constexpr int ROWB  = 80;             // padded row bytes (32 elems * 2B = 64B data)
constexpr int TILEB = 128 * ROWB;     // 10240 B

template <int MODE, int PASSES, bool FP16MMA, bool AF32>
__global__ void __launch_bounds__(256, 2)
mma_gemm(const uint16_t* __restrict__ Ah, const uint16_t* __restrict__ Al,
         const float* __restrict__ Af,
         const uint16_t* __restrict__ Bh, const uint16_t* __restrict__ Bl,
         float* __restrict__ Cf, uint16_t* __restrict__ Ch, uint16_t* __restrict__ Cl,
         const float* __restrict__ aux,
         int M, int N, int K, long sA, long sB, long sC, long sAux, float scale)
{
    constexpr bool HAS_BIAS  = (MODE & 1)  != 0;
    constexpr bool HAS_SCALE = (MODE & 2)  != 0;
    constexpr bool HAS_RES   = (MODE & 4)  != 0;
    constexpr bool WR_F32    = (MODE & 8)  != 0;
    constexpr bool WR_SPB    = (MODE & 16) != 0;
    constexpr bool WR_SPH    = (MODE & 32) != 0;
    constexpr int  NTILES    = (PASSES == 3) ? 4 : 3;
    constexpr int  BTILE     = 2;     // B hi tile index

    extern __shared__ __align__(128) char dsm[];
    const uint32_t sbase = smem_u32(dsm);
    #define TILE(s, t) (sbase + ((s) * NTILES + (t)) * TILEB)

    const int tid  = threadIdx.x;
    const int wid  = tid >> 5;
    const int lane = tid & 31;

    const long z = blockIdx.z;
    if (!AF32) { Ah += z * sA; Al += z * sA; }
    else       { Af += z * sA; }
    Bh += z * sB;
    if (PASSES == 3) Bl += z * sB;
    const long cOff = z * sC;

    const int m0 = blockIdx.y * 128;
    const int n0 = blockIdx.x * 128;

    // cp.async loader geometry: per tile 128 rows x 64B, 2x16B per thread
    const int lrow = tid >> 2;           // 0..63
    const int lkg  = tid & 3;            // 16B group
    auto load_chunk = [&](int s, int k0) {
        if (!AF32) {
            const uint16_t* gA[2] = { Ah + (long)m0 * K + k0, Al + (long)m0 * K + k0 };
#pragma unroll
            for (int t = 0; t < 2; t++) {
                const uint32_t st = TILE(s, t);
#pragma unroll
                for (int h = 0; h < 2; h++) {
                    int row = lrow + h * 64;
                    CP_ASYNC16(st + row * ROWB + lkg * 16, gA[t] + (long)row * K + lkg * 8);
                }
            }
        }
        {
            const uint16_t* g = Bh + (long)n0 * K + k0;
            const uint32_t st = TILE(s, BTILE);
#pragma unroll
            for (int h = 0; h < 2; h++) {
                int row = lrow + h * 64;
                CP_ASYNC16(st + row * ROWB + lkg * 16, g + (long)row * K + lkg * 8);
            }
        }
        if (PASSES == 3) {
            const uint16_t* g = Bl + (long)n0 * K + k0;
            const uint32_t st = TILE(s, 3);
#pragma unroll
            for (int h = 0; h < 2; h++) {
                int row = lrow + h * 64;
                CP_ASYNC16(st + row * ROWB + lkg * 16, g + (long)row * K + lkg * 8);
            }
        }
    };

    // AF32: fp32 A tile via LDG -> fp16 split -> STS  (4 float4 per thread)
    float4 areg[4];
    auto ldgA = [&](int k0) {
        if (AF32) {
#pragma unroll
            for (int j = 0; j < 4; j++) {
                int idx = tid + j * 256;
                int row = idx >> 3, c = idx & 7;
                areg[j] = *reinterpret_cast<const float4*>(
                    Af + (long)(m0 + row) * K + k0 + c * 4);
            }
        }
    };
    auto stsA = [&](int s) {
        if (AF32) {
#pragma unroll
            for (int j = 0; j < 4; j++) {
                int idx = tid + j * 256;
                int row = idx >> 3, c = idx & 7;
                uint16_t h0,l0,h1,l1,h2,l2,h3,l3;
                split_h(areg[j].x, h0, l0); split_h(areg[j].y, h1, l1);
                split_h(areg[j].z, h2, l2); split_h(areg[j].w, h3, l3);
                uint32_t off = (uint32_t)(row * ROWB + c * 8);
                *reinterpret_cast<uint2*>(dsm + (TILE(s,0) - sbase) + off) =
                    make_uint2(pk(h0,h1), pk(h2,h3));
                *reinterpret_cast<uint2*>(dsm + (TILE(s,1) - sbase) + off) =
                    make_uint2(pk(l0,l1), pk(l2,l3));
            }
        }
    };

    float acc[4][4][4];
#pragma unroll
    for (int a = 0; a < 4; a++)
#pragma unroll
        for (int b = 0; b < 4; b++)
#pragma unroll
            for (int c = 0; c < 4; c++) acc[a][b][c] = 0.0f;

    const int nch = K >> 5;

    // prologue
    if (AF32) { ldgA(0); stsA(0); if (nch > 1) ldgA(32); }
    load_chunk(0, 0);
    CP_COMMIT();

    // warp layout: 2 (m) x 4 (n); warp tile 64x32
    const int m0w = (wid & 1) * 64;
    const int n0w = (wid >> 1) * 32;
    const int a_r = lane & 15;
    const int a_h = lane >> 4;
    const int b_r = lane & 7;
    const int b_q = lane >> 3;

    for (int i = 0; i < nch; i++) {
        const int s = i & 1;
        if (i + 1 < nch) {
            const int ns = s ^ 1;
            if (AF32) { stsA(ns); if (i + 2 < nch) ldgA((i + 2) * 32); }
            load_chunk(ns, (i + 1) * 32);
            CP_COMMIT();
            CP_WAIT1();
        } else {
            CP_WAIT0();
        }
        __syncthreads();

        const uint32_t Abh = TILE(s, 0), Abl = TILE(s, 1);
        const uint32_t Bbh = TILE(s, BTILE);
        const uint32_t Bbl = (PASSES == 3) ? TILE(s, 3) : 0;

#pragma unroll
        for (int ks = 0; ks < 2; ks++) {
            const int koff = ks * 32;
            uint32_t bh[8], bl[8];
#pragma unroll
            for (int j = 0; j < 2; j++) {
                uint32_t boff = (uint32_t)((n0w + j * 16 + (b_q >> 1) * 8 + b_r) * ROWB
                                           + koff + (b_q & 1) * 16);
                LDSM_X4(bh[j*4+0], bh[j*4+1], bh[j*4+2], bh[j*4+3], Bbh + boff);
                if (PASSES == 3)
                    LDSM_X4(bl[j*4+0], bl[j*4+1], bl[j*4+2], bl[j*4+3], Bbl + boff);
            }
#pragma unroll
            for (int mi = 0; mi < 4; mi++) {
                uint32_t aoff = (uint32_t)((m0w + mi * 16 + a_r) * ROWB + koff + a_h * 16);
                uint32_t ahr[4], alr[4];
                LDSM_X4(ahr[0], ahr[1], ahr[2], ahr[3], Abh + aoff);
                LDSM_X4(alr[0], alr[1], alr[2], alr[3], Abl + aoff);
#pragma unroll
                for (int ni = 0; ni < 4; ni++) {
                    mma16<FP16MMA>(acc[mi][ni], ahr, bh[ni*2], bh[ni*2+1]);
                    if (PASSES == 3) {
                        mma16<FP16MMA>(acc[mi][ni], ahr, bl[ni*2], bl[ni*2+1]);
                        mma16<FP16MMA>(acc[mi][ni], alr, bh[ni*2], bh[ni*2+1]);
                    } else {
                        mma16<FP16MMA>(acc[mi][ni], alr, bh[ni*2], bh[ni*2+1]);
                    }
                }
            }
        }
        __syncthreads();
    }

    // ---- epilogue ----
    const float* auxp = aux;
    if (HAS_RES) auxp += z * sAux;
    const int crow = lane >> 2;
    const int ccol = (lane & 3) * 2;
#pragma unroll
    for (int mi = 0; mi < 4; mi++) {
#pragma unroll
        for (int rh = 0; rh < 2; rh++) {
            const long row = m0 + m0w + mi * 16 + crow + rh * 8;
#pragma unroll
            for (int ni = 0; ni < 4; ni++) {
                const int col = n0 + n0w + ni * 8 + ccol;
                float v0 = acc[mi][ni][rh * 2];
                float v1 = acc[mi][ni][rh * 2 + 1];
                if (HAS_BIAS)  { v0 += aux[col]; v1 += aux[col + 1]; }
                if (HAS_SCALE) { v0 *= scale; v1 *= scale; }
                if (HAS_RES)   {
                    v0 += auxp[row * (long)N + col];
                    v1 += auxp[row * (long)N + col + 1];
                }
                if (WR_F32)
                    *reinterpret_cast<float2*>(Cf + cOff + row * (long)N + col) =
                        make_float2(v0, v1);
                if (WR_SPB) {
                    uint16_t h0,l0,h1,l1;
                    split_bf(v0, h0, l0); split_bf(v1, h1, l1);
                    *reinterpret_cast<uint32_t*>(Ch + cOff + row * (long)N + col) = pk(h0, h1);
                    *reinterpret_cast<uint32_t*>(Cl + cOff + row * (long)N + col) = pk(l0, l1);
                }
                if (WR_SPH) {
                    uint16_t h0,l0,h1,l1;
                    split_h(v0, h0, l0); split_h(v1, h1, l1);
                    *reinterpret_cast<uint32_t*>(Ch + cOff + row * (long)N + col) = pk(h0, h1);
                    *reinterpret_cast<uint32_t*>(Cl + cOff + row * (long)N + col) = pk(l0, l1);
                }
            }
        }
    }
    #undef TILE
}

// ---------------------------------------------------------------------------
// In-place fp32 row softmax over 2048 columns.
// ---------------------------------------------------------------------------
__global__ void __launch_bounds__(256)
softmax_rows(float* __restrict__ att)
{
    const long row = blockIdx.x;
    float* p = att + row * (long)SKV;
    const int t = threadIdx.x;

    float v[8];
    float m = -INFINITY;
#pragma unroll
    for (int i = 0; i < 8; i++) {
        v[i] = p[t + i * 256];
        m = fmaxf(m, v[i]);
    }
    __shared__ float red[256];
    red[t] = m;
    __syncthreads();
#pragma unroll
    for (int s = 128; s > 0; s >>= 1) {
        if (t < s) red[t] = fmaxf(red[t], red[t + s]);
        __syncthreads();
    }
    m = red[0];
    __syncthreads();
    float sum = 0.0f;
#pragma unroll
    for (int i = 0; i < 8; i++) {
        v[i] = expf(v[i] - m);
        sum += v[i];
    }
    red[t] = sum;
    __syncthreads();
#pragma unroll
    for (int s = 128; s > 0; s >>= 1) {
        if (t < s) red[t] += red[t + s];
        __syncthreads();
    }
    const float inv = 1.0f / red[0];
#pragma unroll
    for (int i = 0; i < 8; i++)
        p[t + i * 256] = v[i] * inv;
}

// ---------------------------------------------------------------------------
extern "C" void kernel_launch(void* const* d_in, const int* in_sizes, int n_in,
                              void* d_out, int out_size)
{
    const float* x  = (const float*)d_in[0];
    const float* en = (const float*)d_in[1];
    const float* Wq = (const float*)d_in[2];
    const float* bq = (const float*)d_in[3];
    const float* Wf = (const float*)d_in[4];
    const float* bf = (const float*)d_in[5];

    float* out  = (float*)d_out;
    float* proj = out;
    float* att  = out + PROJ_ELEMS;

    auto sym = [](const void* s) {
        void* p = nullptr;
        cudaGetSymbolAddress(&p, s);
        return p;
    };
    uint16_t* xh   = (uint16_t*)sym(g_xh);
    uint16_t* xl   = (uint16_t*)sym(g_xl);
    uint16_t* wqT  = (uint16_t*)sym(g_wqT);
    uint16_t* enhi = (uint16_t*)sym(g_enhi);
    uint16_t* enlo = (uint16_t*)sym(g_enlo);
    uint16_t* enT  = (uint16_t*)sym(g_enT);
    uint16_t* wfT  = (uint16_t*)sym(g_wfT);
    float*    qf   = (float*)   sym(g_q);
    uint16_t* qhi  = (uint16_t*)sym(g_qhi);
    uint16_t* qlo  = (uint16_t*)sym(g_qlo);
    uint16_t* sumh = (uint16_t*)sym(g_sumh);
    uint16_t* suml = (uint16_t*)sym(g_suml);

    constexpr int SMEM3 = 2 * 4 * TILEB;   // 81920
    constexpr int SMEM2 = 2 * 3 * TILEB;   // 61440
    cudaFuncSetAttribute(mma_gemm<25, 2, true,  false>, cudaFuncAttributeMaxDynamicSharedMemorySize, SMEM2);
    cudaFuncSetAttribute(mma_gemm<10, 3, false, false>, cudaFuncAttributeMaxDynamicSharedMemorySize, SMEM3);
    cudaFuncSetAttribute(mma_gemm<36, 2, true,  true >, cudaFuncAttributeMaxDynamicSharedMemorySize, SMEM2);
    cudaFuncSetAttribute(mma_gemm<9,  2, true,  false>, cudaFuncAttributeMaxDynamicSharedMemorySize, SMEM2);

    const float scale = 0.044194173824159216f;  // 1/sqrt(512)

    // --- pre-passes ---
    {
        long n4 = (long)BATCH * SQ * DIN / 4;
        split_plain_f16<<<(unsigned)((n4 + 255) / 256), 256>>>(x, xh, xl, n4);
    }
    split_en_fused<<<dim3(DEMB / 32, SKV / 32, BATCH), dim3(32, 8)>>>(en, enhi, enlo, enT);
    conv_T_f16<<<dim3(DEMB / 32, DIN / 32, 1), dim3(32, 8)>>>(Wq, wqT, DIN, DEMB);
    conv_T_f16<<<dim3(DOUT / 32, DEMB / 32, 1), dim3(32, 8)>>>(Wf, wfT, DEMB, DOUT);

    // 1) q = x @ wqT^T + bq   fp16x2, writes q fp32 + bf16 split
    mma_gemm<25, 2, true, false><<<dim3(DEMB / 128, (BATCH * SQ) / 128, 1), 256, SMEM2>>>(
        xh, xl, nullptr, wqT, nullptr, qf, qhi, qlo, bq,
        BATCH * SQ, DEMB, DIN, 0, 0, 0, 0, 0.0f);

    // 2) scores = q @ en^T * scale   bf16x3, fp32 att
    mma_gemm<10, 3, false, false><<<dim3(SKV / 128, SQ / 128, BATCH), 256, SMEM3>>>(
        qhi, qlo, nullptr, enhi, enlo, att, nullptr, nullptr, nullptr,
        SQ, SKV, DEMB,
        (long)SQ * DEMB, (long)SKV * DEMB, (long)SQ * SKV, 0, scale);

    // 3) softmax in-place fp32
    softmax_rows<<<BATCH * SQ, 256>>>(att);

    // 4) sum = att @ enT^T + q   fp16x2, A from fp32 att, writes fp16 split
    mma_gemm<36, 2, true, true><<<dim3(DEMB / 128, SQ / 128, BATCH), 256, SMEM2>>>(
        nullptr, nullptr, att, enT, nullptr, nullptr, sumh, suml, qf,
        SQ, DEMB, SKV,
        (long)SQ * SKV, (long)DEMB * SKV, (long)SQ * DEMB, (long)SQ * DEMB, 0.0f);

    // 5) proj = sum @ wfT^T + bf   fp16x2, fp32 out
    mma_gemm<9, 2, true, false><<<dim3(DOUT / 128, (BATCH * SQ) / 128, 1), 256, SMEM2>>>(
        sumh, suml, nullptr, wfT, nullptr, proj, nullptr, nullptr, bf,
        BATCH * SQ, DOUT, DEMB, 0, 0, 0, 0, 0.0f);

    (void)in_sizes; (void)n_in; (void)out_size;
}

// round 6
// speedup vs baseline: 3.5209x; 1.1149x over previous
#include <cuda_runtime.h>
#include <cuda_fp16.h>
#include <math.h>
#include <stdint.h>

// ---------------------------------------------------------------------------
// Problem constants
// ---------------------------------------------------------------------------
constexpr int BATCH = 8;
constexpr int SQ    = 2048;
constexpr int SKV   = 2048;
constexpr int DIN   = 1024;
constexpr int DEMB  = 512;
constexpr int DOUT  = 512;

constexpr long PROJ_ELEMS = (long)BATCH * SQ * DOUT;

// ---------------------------------------------------------------------------
// Scratch (device globals; no allocation allowed)
// ---------------------------------------------------------------------------
__device__ __align__(16) uint16_t g_xh [(long)BATCH * SQ * DIN];    // fp16 hi
__device__ __align__(16) uint16_t g_xl [(long)BATCH * SQ * DIN];    // fp16 lo
__device__ __align__(16) uint16_t g_wqT[DEMB * DIN];                // fp16
__device__ __align__(16) uint16_t g_enS[(long)BATCH * SKV * DEMB];  // fp16, K-major
__device__ __align__(16) uint16_t g_enT[(long)BATCH * DEMB * SKV];  // fp16, transposed
__device__ __align__(16) uint16_t g_wfT[DOUT * DEMB];               // fp16
__device__ __align__(16) float    g_q  [(long)BATCH * SQ * DEMB];   // fp32 (residual)
__device__ __align__(16) uint16_t g_qh [(long)BATCH * SQ * DEMB];   // fp16 hi
__device__ __align__(16) uint16_t g_ql [(long)BATCH * SQ * DEMB];   // fp16 lo
__device__ __align__(16) uint16_t g_sumh[(long)BATCH * SQ * DEMB];  // fp16 hi
__device__ __align__(16) uint16_t g_suml[(long)BATCH * SQ * DEMB];  // fp16 lo

// ---------------------------------------------------------------------------
// PTX helpers (sm_80-compatible path: mma.sync / ldmatrix / cp.async)
// ---------------------------------------------------------------------------
__device__ __forceinline__ uint32_t smem_u32(const void* p) {
    uint32_t a;
    asm("{ .reg .u64 t; cvta.to.shared.u64 t, %1; cvt.u32.u64 %0, t; }" : "=r"(a) : "l"(p));
    return a;
}

#define CP_ASYNC16(dst, src) \
    asm volatile("cp.async.cg.shared.global [%0], [%1], 16;" :: "r"(dst), "l"(src))
#define CP_COMMIT()  asm volatile("cp.async.commit_group;" ::: "memory")
#define CP_WAIT0()   asm volatile("cp.async.wait_group 0;" ::: "memory")
#define CP_WAIT1()   asm volatile("cp.async.wait_group 1;" ::: "memory")

#define LDSM_X4(r0, r1, r2, r3, addr) \
    asm volatile("ldmatrix.sync.aligned.m8n8.x4.shared.b16 {%0,%1,%2,%3}, [%4];" \
                 : "=r"(r0), "=r"(r1), "=r"(r2), "=r"(r3) : "r"(addr))

__device__ __forceinline__ void mma_h(float* d, const uint32_t* a, uint32_t b0, uint32_t b1) {
    asm volatile("mma.sync.aligned.m16n8k16.row.col.f32.f16.f16.f32 "
                 "{%0,%1,%2,%3}, {%4,%5,%6,%7}, {%8,%9}, {%0,%1,%2,%3};"
                 : "+f"(d[0]), "+f"(d[1]), "+f"(d[2]), "+f"(d[3])
                 : "r"(a[0]), "r"(a[1]), "r"(a[2]), "r"(a[3]), "r"(b0), "r"(b1));
}

// ---------------------------------------------------------------------------
// split helpers
// ---------------------------------------------------------------------------
__device__ __forceinline__ void split_h(float v, uint16_t& h, uint16_t& l) {
    __half hh = __float2half_rn(v);
    __half ll = __float2half_rn(v - __half2float(hh));
    h = __half_as_ushort(hh);
    l = __half_as_ushort(ll);
}
__device__ __forceinline__ uint32_t pk(uint16_t a, uint16_t b) {
    return (uint32_t)a | ((uint32_t)b << 16);
}

// ---------------------------------------------------------------------------
// Pre-pass kernels
// ---------------------------------------------------------------------------
// x -> fp16 hi/lo
__global__ void __launch_bounds__(256)
split_plain_f16(const float* __restrict__ src, uint16_t* __restrict__ hi,
                uint16_t* __restrict__ lo, long n4)
{
    long i = (long)blockIdx.x * 256 + threadIdx.x;
    if (i >= n4) return;
    float4 v = reinterpret_cast<const float4*>(src)[i];
    uint16_t h0,l0,h1,l1,h2,l2,h3,l3;
    split_h(v.x,h0,l0); split_h(v.y,h1,l1);
    split_h(v.z,h2,l2); split_h(v.w,h3,l3);
    reinterpret_cast<uint2*>(hi)[i] = make_uint2(pk(h0,h1), pk(h2,h3));
    reinterpret_cast<uint2*>(lo)[i] = make_uint2(pk(l0,l1), pk(l2,l3));
}

// en -> fp16 single (same layout) + fp16 single transposed [DEMB, SKV]
__global__ void __launch_bounds__(256)
conv_en_fused(const float* __restrict__ en, uint16_t* __restrict__ eS,
              uint16_t* __restrict__ eT)
{
    const long z = blockIdx.z;
    en += z * (long)SKV * DEMB;
    eS += z * (long)SKV * DEMB;
    eT += z * (long)DEMB * SKV;
    __shared__ float t[32][33];
    const int c0 = blockIdx.x * 32;   // DEMB
    const int r0 = blockIdx.y * 32;   // SKV
    const int tx = threadIdx.x, ty = threadIdx.y;
#pragma unroll
    for (int j = 0; j < 4; j++) {
        int r = r0 + ty + j * 8;
        float v = en[(long)r * DEMB + c0 + tx];
        t[ty + j * 8][tx] = v;
        eS[(long)r * DEMB + c0 + tx] = __half_as_ushort(__float2half_rn(v));
    }
    __syncthreads();
#pragma unroll
    for (int j = 0; j < 4; j++) {
        int c = c0 + ty + j * 8;
        eT[(long)c * SKV + r0 + tx] =
            __half_as_ushort(__float2half_rn(t[tx][ty + j * 8]));
    }
}

// W [R,C] fp32 -> WT [C,R] fp16 single
__global__ void __launch_bounds__(256)
conv_T_f16(const float* __restrict__ src, uint16_t* __restrict__ dstT, int R, int C)
{
    __shared__ float t[32][33];
    const int c0 = blockIdx.x * 32;
    const int r0 = blockIdx.y * 32;
    const int tx = threadIdx.x, ty = threadIdx.y;
#pragma unroll
    for (int j = 0; j < 4; j++) {
        int r = r0 + ty + j * 8;
        t[ty + j * 8][tx] = src[(long)r * C + c0 + tx];
    }
    __syncthreads();
#pragma unroll
    for (int j = 0; j < 4; j++) {
        int c = c0 + ty + j * 8;
        dstT[(long)c * R + r0 + tx] = __half_as_ushort(__float2half_rn(t[tx][ty + j * 8]));
    }
}

// ---------------------------------------------------------------------------
// fp16x2 HMMA GEMM: C[M,N] = A[M,K] @ B[N,K]^T (+epilogue)
// A given as fp16 (hi, lo); B single fp16. 3 SMEM tiles per stage.
// AF32: A read as fp32 and split to fp16 hi/lo in the loader (att matrix).
// MODE bits: 1=bias, 2=scale, 4=residual, 8=write fp32, 32=write fp16 split
// ---------------------------------------------------------------------------
constexpr int ROWB  = 80;             // padded row bytes (32 elems * 2B = 64B data)
constexpr int TILEB = 128 * ROWB;     // 10240 B
constexpr int SMEM_BYTES = 2 * 3 * TILEB;  // 61440

template <int MODE, bool AF32>
__global__ void __launch_bounds__(256, 2)
mma_gemm(const uint16_t* __restrict__ Ah, const uint16_t* __restrict__ Al,
         const float* __restrict__ Af, const uint16_t* __restrict__ Bs,
         float* __restrict__ Cf, uint16_t* __restrict__ Ch, uint16_t* __restrict__ Cl,
         const float* __restrict__ aux,
         int M, int N, int K, long sA, long sB, long sC, long sAux, float scale)
{
    constexpr bool HAS_BIAS  = (MODE & 1)  != 0;
    constexpr bool HAS_SCALE = (MODE & 2)  != 0;
    constexpr bool HAS_RES   = (MODE & 4)  != 0;
    constexpr bool WR_F32    = (MODE & 8)  != 0;
    constexpr bool WR_SPH    = (MODE & 32) != 0;

    extern __shared__ __align__(128) char dsm[];
    const uint32_t sbase = smem_u32(dsm);
    #define TILE(s, t) (sbase + ((s) * 3 + (t)) * TILEB)

    const int tid  = threadIdx.x;
    const int wid  = tid >> 5;
    const int lane = tid & 31;

    const long z = blockIdx.z;
    if (!AF32) { Ah += z * sA; Al += z * sA; }
    else       { Af += z * sA; }
    Bs += z * sB;
    const long cOff = z * sC;

    const int m0 = blockIdx.y * 128;
    const int n0 = blockIdx.x * 128;

    const int lrow = tid >> 2;           // 0..63
    const int lkg  = tid & 3;            // 16B group
    auto load_chunk = [&](int s, int k0) {
        if (!AF32) {
            const uint16_t* gA[2] = { Ah + (long)m0 * K + k0, Al + (long)m0 * K + k0 };
#pragma unroll
            for (int t = 0; t < 2; t++) {
                const uint32_t st = TILE(s, t);
#pragma unroll
                for (int h = 0; h < 2; h++) {
                    int row = lrow + h * 64;
                    CP_ASYNC16(st + row * ROWB + lkg * 16, gA[t] + (long)row * K + lkg * 8);
                }
            }
        }
        {
            const uint16_t* g = Bs + (long)n0 * K + k0;
            const uint32_t st = TILE(s, 2);
#pragma unroll
            for (int h = 0; h < 2; h++) {
                int row = lrow + h * 64;
                CP_ASYNC16(st + row * ROWB + lkg * 16, g + (long)row * K + lkg * 8);
            }
        }
    };

    // AF32: fp32 A tile via LDG -> fp16 split -> STS
    float4 areg[4];
    auto ldgA = [&](int k0) {
        if (AF32) {
#pragma unroll
            for (int j = 0; j < 4; j++) {
                int idx = tid + j * 256;
                int row = idx >> 3, c = idx & 7;
                areg[j] = *reinterpret_cast<const float4*>(
                    Af + (long)(m0 + row) * K + k0 + c * 4);
            }
        }
    };
    auto stsA = [&](int s) {
        if (AF32) {
#pragma unroll
            for (int j = 0; j < 4; j++) {
                int idx = tid + j * 256;
                int row = idx >> 3, c = idx & 7;
                uint16_t h0,l0,h1,l1,h2,l2,h3,l3;
                split_h(areg[j].x, h0, l0); split_h(areg[j].y, h1, l1);
                split_h(areg[j].z, h2, l2); split_h(areg[j].w, h3, l3);
                uint32_t off = (uint32_t)(row * ROWB + c * 8);
                *reinterpret_cast<uint2*>(dsm + (TILE(s,0) - sbase) + off) =
                    make_uint2(pk(h0,h1), pk(h2,h3));
                *reinterpret_cast<uint2*>(dsm + (TILE(s,1) - sbase) + off) =
                    make_uint2(pk(l0,l1), pk(l2,l3));
            }
        }
    };

    float acc[4][4][4];
#pragma unroll
    for (int a = 0; a < 4; a++)
#pragma unroll
        for (int b = 0; b < 4; b++)
#pragma unroll
            for (int c = 0; c < 4; c++) acc[a][b][c] = 0.0f;

    const int nch = K >> 5;

    if (AF32) { ldgA(0); stsA(0); if (nch > 1) ldgA(32); }
    load_chunk(0, 0);
    CP_COMMIT();

    // warp layout: 2 (m) x 4 (n); warp tile 64x32
    const int m0w = (wid & 1) * 64;
    const int n0w = (wid >> 1) * 32;
    const int a_r = lane & 15;
    const int a_h = lane >> 4;
    const int b_r = lane & 7;
    const int b_q = lane >> 3;

    for (int i = 0; i < nch; i++) {
        const int s = i & 1;
        if (i + 1 < nch) {
            const int ns = s ^ 1;
            if (AF32) { stsA(ns); if (i + 2 < nch) ldgA((i + 2) * 32); }
            load_chunk(ns, (i + 1) * 32);
            CP_COMMIT();
            CP_WAIT1();
        } else {
            CP_WAIT0();
        }
        __syncthreads();

        const uint32_t Abh = TILE(s, 0), Abl = TILE(s, 1), Bb = TILE(s, 2);

#pragma unroll
        for (int ks = 0; ks < 2; ks++) {
            const int koff = ks * 32;
            uint32_t bh[8];
#pragma unroll
            for (int j = 0; j < 2; j++) {
                uint32_t boff = (uint32_t)((n0w + j * 16 + (b_q >> 1) * 8 + b_r) * ROWB
                                           + koff + (b_q & 1) * 16);
                LDSM_X4(bh[j*4+0], bh[j*4+1], bh[j*4+2], bh[j*4+3], Bb + boff);
            }
#pragma unroll
            for (int mi = 0; mi < 4; mi++) {
                uint32_t aoff = (uint32_t)((m0w + mi * 16 + a_r) * ROWB + koff + a_h * 16);
                uint32_t ahr[4], alr[4];
                LDSM_X4(ahr[0], ahr[1], ahr[2], ahr[3], Abh + aoff);
                LDSM_X4(alr[0], alr[1], alr[2], alr[3], Abl + aoff);
#pragma unroll
                for (int ni = 0; ni < 4; ni++) {
                    mma_h(acc[mi][ni], ahr, bh[ni*2], bh[ni*2+1]);
                    mma_h(acc[mi][ni], alr, bh[ni*2], bh[ni*2+1]);
                }
            }
        }
        __syncthreads();
    }

    // ---- epilogue ----
    const float* auxp = aux;
    if (HAS_RES) auxp += z * sAux;
    const int crow = lane >> 2;
    const int ccol = (lane & 3) * 2;
#pragma unroll
    for (int mi = 0; mi < 4; mi++) {
#pragma unroll
        for (int rh = 0; rh < 2; rh++) {
            const long row = m0 + m0w + mi * 16 + crow + rh * 8;
#pragma unroll
            for (int ni = 0; ni < 4; ni++) {
                const int col = n0 + n0w + ni * 8 + ccol;
                float v0 = acc[mi][ni][rh * 2];
                float v1 = acc[mi][ni][rh * 2 + 1];
                if (HAS_BIAS)  { v0 += aux[col]; v1 += aux[col + 1]; }
                if (HAS_SCALE) { v0 *= scale; v1 *= scale; }
                if (HAS_RES)   {
                    v0 += auxp[row * (long)N + col];
                    v1 += auxp[row * (long)N + col + 1];
                }
                if (WR_F32)
                    *reinterpret_cast<float2*>(Cf + cOff + row * (long)N + col) =
                        make_float2(v0, v1);
                if (WR_SPH) {
                    uint16_t h0,l0,h1,l1;
                    split_h(v0, h0, l0); split_h(v1, h1, l1);
                    *reinterpret_cast<uint32_t*>(Ch + cOff + row * (long)N + col) = pk(h0, h1);
                    *reinterpret_cast<uint32_t*>(Cl + cOff + row * (long)N + col) = pk(l0, l1);
                }
            }
        }
    }
    #undef TILE
}

// ---------------------------------------------------------------------------
// In-place fp32 row softmax over 2048 columns, shuffle reductions.
// ---------------------------------------------------------------------------
__global__ void __launch_bounds__(256)
softmax_rows(float* __restrict__ att)
{
    const long row = blockIdx.x;
    float* p = att + row * (long)SKV;
    const int t = threadIdx.x;
    const int w = t >> 5, ln = t & 31;
    __shared__ float red[8];

    float v[8];
    float m = -INFINITY;
#pragma unroll
    for (int i = 0; i < 8; i++) {
        v[i] = p[t + i * 256];
        m = fmaxf(m, v[i]);
    }
#pragma unroll
    for (int s = 16; s > 0; s >>= 1)
        m = fmaxf(m, __shfl_xor_sync(0xFFFFFFFFu, m, s));
    if (ln == 0) red[w] = m;
    __syncthreads();
    m = red[ln & 7];
#pragma unroll
    for (int s = 4; s > 0; s >>= 1)
        m = fmaxf(m, __shfl_xor_sync(0xFFFFFFFFu, m, s));

    float sum = 0.0f;
#pragma unroll
    for (int i = 0; i < 8; i++) {
        v[i] = __expf(v[i] - m);
        sum += v[i];
    }
#pragma unroll
    for (int s = 16; s > 0; s >>= 1)
        sum += __shfl_xor_sync(0xFFFFFFFFu, sum, s);
    __syncthreads();
    if (ln == 0) red[w] = sum;
    __syncthreads();
    sum = red[ln & 7];
#pragma unroll
    for (int s = 4; s > 0; s >>= 1)
        sum += __shfl_xor_sync(0xFFFFFFFFu, sum, s);

    const float inv = 1.0f / sum;
#pragma unroll
    for (int i = 0; i < 8; i++)
        p[t + i * 256] = v[i] * inv;
}

// ---------------------------------------------------------------------------
extern "C" void kernel_launch(void* const* d_in, const int* in_sizes, int n_in,
                              void* d_out, int out_size)
{
    const float* x  = (const float*)d_in[0];
    const float* en = (const float*)d_in[1];
    const float* Wq = (const float*)d_in[2];
    const float* bq = (const float*)d_in[3];
    const float* Wf = (const float*)d_in[4];
    const float* bf = (const float*)d_in[5];

    float* out  = (float*)d_out;
    float* proj = out;
    float* att  = out + PROJ_ELEMS;

    auto sym = [](const void* s) {
        void* p = nullptr;
        cudaGetSymbolAddress(&p, s);
        return p;
    };
    uint16_t* xh   = (uint16_t*)sym(g_xh);
    uint16_t* xl   = (uint16_t*)sym(g_xl);
    uint16_t* wqT  = (uint16_t*)sym(g_wqT);
    uint16_t* enS  = (uint16_t*)sym(g_enS);
    uint16_t* enT  = (uint16_t*)sym(g_enT);
    uint16_t* wfT  = (uint16_t*)sym(g_wfT);
    float*    qf   = (float*)   sym(g_q);
    uint16_t* qh   = (uint16_t*)sym(g_qh);
    uint16_t* ql   = (uint16_t*)sym(g_ql);
    uint16_t* sumh = (uint16_t*)sym(g_sumh);
    uint16_t* suml = (uint16_t*)sym(g_suml);

    cudaFuncSetAttribute(mma_gemm<41, false>, cudaFuncAttributeMaxDynamicSharedMemorySize, SMEM_BYTES);
    cudaFuncSetAttribute(mma_gemm<10, false>, cudaFuncAttributeMaxDynamicSharedMemorySize, SMEM_BYTES);
    cudaFuncSetAttribute(mma_gemm<36, true >, cudaFuncAttributeMaxDynamicSharedMemorySize, SMEM_BYTES);
    cudaFuncSetAttribute(mma_gemm<9,  false>, cudaFuncAttributeMaxDynamicSharedMemorySize, SMEM_BYTES);

    const float scale = 0.044194173824159216f;  // 1/sqrt(512)

    // --- pre-passes ---
    {
        long n4 = (long)BATCH * SQ * DIN / 4;
        split_plain_f16<<<(unsigned)((n4 + 255) / 256), 256>>>(x, xh, xl, n4);
    }
    conv_en_fused<<<dim3(DEMB / 32, SKV / 32, BATCH), dim3(32, 8)>>>(en, enS, enT);
    conv_T_f16<<<dim3(DEMB / 32, DIN / 32, 1), dim3(32, 8)>>>(Wq, wqT, DIN, DEMB);
    conv_T_f16<<<dim3(DOUT / 32, DEMB / 32, 1), dim3(32, 8)>>>(Wf, wfT, DEMB, DOUT);

    // 1) q = x @ wqT^T + bq    (fp32 q + fp16 split)   MODE = bias|f32|sph = 41
    mma_gemm<41, false><<<dim3(DEMB / 128, (BATCH * SQ) / 128, 1), 256, SMEM_BYTES>>>(
        xh, xl, nullptr, wqT, qf, qh, ql, bq,
        BATCH * SQ, DEMB, DIN, 0, 0, 0, 0, 0.0f);

    // 2) scores = q @ enS^T * scale   fp16x2, fp32 att  MODE = scale|f32 = 10
    mma_gemm<10, false><<<dim3(SKV / 128, SQ / 128, BATCH), 256, SMEM_BYTES>>>(
        qh, ql, nullptr, enS, att, nullptr, nullptr, nullptr,
        SQ, SKV, DEMB,
        (long)SQ * DEMB, (long)SKV * DEMB, (long)SQ * SKV, 0, scale);

    // 3) softmax in-place fp32
    softmax_rows<<<BATCH * SQ, 256>>>(att);

    // 4) sum = att @ enT^T + q   A from fp32 att, fp16 split out  MODE = res|sph = 36
    mma_gemm<36, true><<<dim3(DEMB / 128, SQ / 128, BATCH), 256, SMEM_BYTES>>>(
        nullptr, nullptr, att, enT, nullptr, sumh, suml, qf,
        SQ, DEMB, SKV,
        (long)SQ * SKV, (long)DEMB * SKV, (long)SQ * DEMB, (long)SQ * DEMB, 0.0f);

    // 5) proj = sum @ wfT^T + bf   fp32 out  MODE = bias|f32 = 9
    mma_gemm<9, false><<<dim3(DOUT / 128, (BATCH * SQ) / 128, 1), 256, SMEM_BYTES>>>(
        sumh, suml, nullptr, wfT, proj, nullptr, nullptr, bf,
        BATCH * SQ, DOUT, DEMB, 0, 0, 0, 0, 0.0f);

    (void)in_sizes; (void)n_in; (void)out_size;
}

// round 8
// speedup vs baseline: 4.1484x; 1.1782x over previous
#include <cuda_runtime.h>
#include <cuda_fp16.h>
#include <math.h>
#include <stdint.h>

// ---------------------------------------------------------------------------
// Problem constants
// ---------------------------------------------------------------------------
constexpr int BATCH = 8;
constexpr int SQ    = 2048;
constexpr int SKV   = 2048;
constexpr int DIN   = 1024;
constexpr int DEMB  = 512;
constexpr int DOUT  = 512;

constexpr long PROJ_ELEMS = (long)BATCH * SQ * DOUT;

// ---------------------------------------------------------------------------
// Scratch (device globals; no allocation allowed)
// ---------------------------------------------------------------------------
__device__ __align__(16) uint16_t g_xh  [(long)BATCH * SQ * DIN];    // fp16 hi
__device__ __align__(16) uint16_t g_xl  [(long)BATCH * SQ * DIN];    // fp16 lo
__device__ __align__(16) uint16_t g_wqT [DEMB * DIN];                // fp16
__device__ __align__(16) uint16_t g_enS [(long)BATCH * SKV * DEMB];  // fp16, K-major
__device__ __align__(16) uint16_t g_enT [(long)BATCH * DEMB * SKV];  // fp16, transposed
__device__ __align__(16) uint16_t g_wfT [DOUT * DEMB];               // fp16
__device__ __align__(16) float    g_q   [(long)BATCH * SQ * DEMB];   // fp32 (residual)
__device__ __align__(16) uint16_t g_qh  [(long)BATCH * SQ * DEMB];   // fp16 hi
__device__ __align__(16) uint16_t g_ql  [(long)BATCH * SQ * DEMB];   // fp16 lo
__device__ __align__(16) uint16_t g_attH[(long)BATCH * SQ * SKV];    // fp16 att (post-softmax)
__device__ __align__(16) uint16_t g_sumh[(long)BATCH * SQ * DEMB];   // fp16 sum

// ---------------------------------------------------------------------------
// PTX helpers (sm_80-compatible path: mma.sync / ldmatrix / cp.async)
// ---------------------------------------------------------------------------
__device__ __forceinline__ uint32_t smem_u32(const void* p) {
    uint32_t a;
    asm("{ .reg .u64 t; cvta.to.shared.u64 t, %1; cvt.u32.u64 %0, t; }" : "=r"(a) : "l"(p));
    return a;
}

#define CP_ASYNC16(dst, src) \
    asm volatile("cp.async.cg.shared.global [%0], [%1], 16;" :: "r"(dst), "l"(src))
#define CP_COMMIT()  asm volatile("cp.async.commit_group;" ::: "memory")
#define CP_WAIT0()   asm volatile("cp.async.wait_group 0;" ::: "memory")
#define CP_WAIT1()   asm volatile("cp.async.wait_group 1;" ::: "memory")

#define LDSM_X4(r0, r1, r2, r3, addr) \
    asm volatile("ldmatrix.sync.aligned.m8n8.x4.shared.b16 {%0,%1,%2,%3}, [%4];" \
                 : "=r"(r0), "=r"(r1), "=r"(r2), "=r"(r3) : "r"(addr))

__device__ __forceinline__ void mma_h(float* d, const uint32_t* a, uint32_t b0, uint32_t b1) {
    asm volatile("mma.sync.aligned.m16n8k16.row.col.f32.f16.f16.f32 "
                 "{%0,%1,%2,%3}, {%4,%5,%6,%7}, {%8,%9}, {%0,%1,%2,%3};"
                 : "+f"(d[0]), "+f"(d[1]), "+f"(d[2]), "+f"(d[3])
                 : "r"(a[0]), "r"(a[1]), "r"(a[2]), "r"(a[3]), "r"(b0), "r"(b1));
}

// ---------------------------------------------------------------------------
// split helpers
// ---------------------------------------------------------------------------
__device__ __forceinline__ void split_h(float v, uint16_t& h, uint16_t& l) {
    __half hh = __float2half_rn(v);
    __half ll = __float2half_rn(v - __half2float(hh));
    h = __half_as_ushort(hh);
    l = __half_as_ushort(ll);
}
__device__ __forceinline__ uint32_t pk(uint16_t a, uint16_t b) {
    return (uint32_t)a | ((uint32_t)b << 16);
}
__device__ __forceinline__ uint16_t h16(float v) {
    return __half_as_ushort(__float2half_rn(v));
}

// ---------------------------------------------------------------------------
// Pre-pass kernels
// ---------------------------------------------------------------------------
__global__ void __launch_bounds__(256)
split_plain_f16(const float* __restrict__ src, uint16_t* __restrict__ hi,
                uint16_t* __restrict__ lo, long n4)
{
    long i = (long)blockIdx.x * 256 + threadIdx.x;
    if (i >= n4) return;
    float4 v = reinterpret_cast<const float4*>(src)[i];
    uint16_t h0,l0,h1,l1,h2,l2,h3,l3;
    split_h(v.x,h0,l0); split_h(v.y,h1,l1);
    split_h(v.z,h2,l2); split_h(v.w,h3,l3);
    reinterpret_cast<uint2*>(hi)[i] = make_uint2(pk(h0,h1), pk(h2,h3));
    reinterpret_cast<uint2*>(lo)[i] = make_uint2(pk(l0,l1), pk(l2,l3));
}

// en -> fp16 single (same layout) + fp16 single transposed [DEMB, SKV]
__global__ void __launch_bounds__(256)
conv_en_fused(const float* __restrict__ en, uint16_t* __restrict__ eS,
              uint16_t* __restrict__ eT)
{
    const long z = blockIdx.z;
    en += z * (long)SKV * DEMB;
    eS += z * (long)SKV * DEMB;
    eT += z * (long)DEMB * SKV;
    __shared__ float t[32][33];
    const int c0 = blockIdx.x * 32;   // DEMB
    const int r0 = blockIdx.y * 32;   // SKV
    const int tx = threadIdx.x, ty = threadIdx.y;
#pragma unroll
    for (int j = 0; j < 4; j++) {
        int r = r0 + ty + j * 8;
        float v = en[(long)r * DEMB + c0 + tx];
        t[ty + j * 8][tx] = v;
        eS[(long)r * DEMB + c0 + tx] = h16(v);
    }
    __syncthreads();
#pragma unroll
    for (int j = 0; j < 4; j++) {
        int c = c0 + ty + j * 8;
        eT[(long)c * SKV + r0 + tx] = h16(t[tx][ty + j * 8]);
    }
}

// W [R,C] fp32 -> WT [C,R] fp16 single
__global__ void __launch_bounds__(256)
conv_T_f16(const float* __restrict__ src, uint16_t* __restrict__ dstT, int R, int C)
{
    __shared__ float t[32][33];
    const int c0 = blockIdx.x * 32;
    const int r0 = blockIdx.y * 32;
    const int tx = threadIdx.x, ty = threadIdx.y;
#pragma unroll
    for (int j = 0; j < 4; j++) {
        int r = r0 + ty + j * 8;
        t[ty + j * 8][tx] = src[(long)r * C + c0 + tx];
    }
    __syncthreads();
#pragma unroll
    for (int j = 0; j < 4; j++) {
        int c = c0 + ty + j * 8;
        dstT[(long)c * R + r0 + tx] = h16(t[tx][ty + j * 8]);
    }
}

// ---------------------------------------------------------------------------
// fp16 HMMA GEMM: C[M,N] = A[M,K] @ B[N,K]^T (+epilogue)
// PASSES=2: A as (hi, lo) fp16 pair, 3 SMEM tiles/stage.
// PASSES=1: A single fp16, 2 SMEM tiles/stage.
// MODE bits: 1=bias, 2=scale, 4=residual, 8=write fp32,
//            16=write fp16 single, 32=write fp16 hi/lo split
// ---------------------------------------------------------------------------
constexpr int ROWB  = 80;             // padded row bytes (32 elems * 2B = 64B data)
constexpr int TILEB = 128 * ROWB;     // 10240 B

template <int MODE, int PASSES>
__global__ void __launch_bounds__(256, 2)
mma_gemm(const uint16_t* __restrict__ Ah, const uint16_t* __restrict__ Al,
         const uint16_t* __restrict__ Bs,
         float* __restrict__ Cf, uint16_t* __restrict__ Ch, uint16_t* __restrict__ Cl,
         const float* __restrict__ aux,
         int M, int N, int K, long sA, long sB, long sC, long sAux, float scale)
{
    constexpr bool HAS_BIAS  = (MODE & 1)  != 0;
    constexpr bool HAS_SCALE = (MODE & 2)  != 0;
    constexpr bool HAS_RES   = (MODE & 4)  != 0;
    constexpr bool WR_F32    = (MODE & 8)  != 0;
    constexpr bool WR_F16    = (MODE & 16) != 0;
    constexpr bool WR_SPH    = (MODE & 32) != 0;
    constexpr int  NT        = PASSES + 1;    // tiles per stage
    constexpr int  BT        = NT - 1;        // B tile index

    extern __shared__ __align__(128) char dsm[];
    const uint32_t sbase = smem_u32(dsm);
    #define TILE(s, t) (sbase + ((s) * NT + (t)) * TILEB)

    const int tid  = threadIdx.x;
    const int wid  = tid >> 5;
    const int lane = tid & 31;

    const long z = blockIdx.z;
    Ah += z * sA;
    if (PASSES == 2) Al += z * sA;
    Bs += z * sB;
    const long cOff = z * sC;

    const int m0 = blockIdx.y * 128;
    const int n0 = blockIdx.x * 128;

    const int lrow = tid >> 2;           // 0..63
    const int lkg  = tid & 3;            // 16B group
    auto load_chunk = [&](int s, int k0) {
        {
            const uint16_t* g = Ah + (long)m0 * K + k0;
            const uint32_t st = TILE(s, 0);
#pragma unroll
            for (int h = 0; h < 2; h++) {
                int row = lrow + h * 64;
                CP_ASYNC16(st + row * ROWB + lkg * 16, g + (long)row * K + lkg * 8);
            }
        }
        if (PASSES == 2) {
            const uint16_t* g = Al + (long)m0 * K + k0;
            const uint32_t st = TILE(s, 1);
#pragma unroll
            for (int h = 0; h < 2; h++) {
                int row = lrow + h * 64;
                CP_ASYNC16(st + row * ROWB + lkg * 16, g + (long)row * K + lkg * 8);
            }
        }
        {
            const uint16_t* g = Bs + (long)n0 * K + k0;
            const uint32_t st = TILE(s, BT);
#pragma unroll
            for (int h = 0; h < 2; h++) {
                int row = lrow + h * 64;
                CP_ASYNC16(st + row * ROWB + lkg * 16, g + (long)row * K + lkg * 8);
            }
        }
    };

    float acc[4][4][4];
#pragma unroll
    for (int a = 0; a < 4; a++)
#pragma unroll
        for (int b = 0; b < 4; b++)
#pragma unroll
            for (int c = 0; c < 4; c++) acc[a][b][c] = 0.0f;

    const int nch = K >> 5;

    load_chunk(0, 0);
    CP_COMMIT();

    // warp layout: 2 (m) x 4 (n); warp tile 64x32
    const int m0w = (wid & 1) * 64;
    const int n0w = (wid >> 1) * 32;
    const int a_r = lane & 15;
    const int a_h = lane >> 4;
    const int b_r = lane & 7;
    const int b_q = lane >> 3;

    for (int i = 0; i < nch; i++) {
        const int s = i & 1;
        if (i + 1 < nch) {
            load_chunk(s ^ 1, (i + 1) * 32);
            CP_COMMIT();
            CP_WAIT1();
        } else {
            CP_WAIT0();
        }
        __syncthreads();

        const uint32_t Abh = TILE(s, 0);
        const uint32_t Abl = (PASSES == 2) ? TILE(s, 1) : 0;
        const uint32_t Bb  = TILE(s, BT);

#pragma unroll
        for (int ks = 0; ks < 2; ks++) {
            const int koff = ks * 32;
            uint32_t bh[8];
#pragma unroll
            for (int j = 0; j < 2; j++) {
                uint32_t boff = (uint32_t)((n0w + j * 16 + (b_q >> 1) * 8 + b_r) * ROWB
                                           + koff + (b_q & 1) * 16);
                LDSM_X4(bh[j*4+0], bh[j*4+1], bh[j*4+2], bh[j*4+3], Bb + boff);
            }
#pragma unroll
            for (int mi = 0; mi < 4; mi++) {
                uint32_t aoff = (uint32_t)((m0w + mi * 16 + a_r) * ROWB + koff + a_h * 16);
                uint32_t ahr[4];
                LDSM_X4(ahr[0], ahr[1], ahr[2], ahr[3], Abh + aoff);
#pragma unroll
                for (int ni = 0; ni < 4; ni++)
                    mma_h(acc[mi][ni], ahr, bh[ni*2], bh[ni*2+1]);
                if (PASSES == 2) {
                    uint32_t alr[4];
                    LDSM_X4(alr[0], alr[1], alr[2], alr[3], Abl + aoff);
#pragma unroll
                    for (int ni = 0; ni < 4; ni++)
                        mma_h(acc[mi][ni], alr, bh[ni*2], bh[ni*2+1]);
                }
            }
        }
        __syncthreads();
    }

    // ---- epilogue ----
    const float* auxp = aux;
    if (HAS_RES) auxp += z * sAux;
    const int crow = lane >> 2;
    const int ccol = (lane & 3) * 2;
#pragma unroll
    for (int mi = 0; mi < 4; mi++) {
#pragma unroll
        for (int rh = 0; rh < 2; rh++) {
            const long row = m0 + m0w + mi * 16 + crow + rh * 8;
#pragma unroll
            for (int ni = 0; ni < 4; ni++) {
                const int col = n0 + n0w + ni * 8 + ccol;
                float v0 = acc[mi][ni][rh * 2];
                float v1 = acc[mi][ni][rh * 2 + 1];
                if (HAS_BIAS)  { v0 += aux[col]; v1 += aux[col + 1]; }
                if (HAS_SCALE) { v0 *= scale; v1 *= scale; }
                if (HAS_RES)   {
                    v0 += auxp[row * (long)N + col];
                    v1 += auxp[row * (long)N + col + 1];
                }
                if (WR_F32)
                    *reinterpret_cast<float2*>(Cf + cOff + row * (long)N + col) =
                        make_float2(v0, v1);
                if (WR_F16)
                    *reinterpret_cast<uint32_t*>(Ch + cOff + row * (long)N + col) =
                        pk(h16(v0), h16(v1));
                if (WR_SPH) {
                    uint16_t h0,l0,h1,l1;
                    split_h(v0, h0, l0); split_h(v1, h1, l1);
                    *reinterpret_cast<uint32_t*>(Ch + cOff + row * (long)N + col) = pk(h0, h1);
                    *reinterpret_cast<uint32_t*>(Cl + cOff + row * (long)N + col) = pk(l0, l1);
                }
            }
        }
    }
    #undef TILE
}

// ---------------------------------------------------------------------------
// In-place fp32 row softmax over 2048 columns + fp16 copy for the A*V GEMM.
// ---------------------------------------------------------------------------
__global__ void __launch_bounds__(256)
softmax_rows(float* __restrict__ att, uint16_t* __restrict__ attH)
{
    const long row = blockIdx.x;
    float* p = att + row * (long)SKV;
    uint16_t* ph = attH + row * (long)SKV;
    const int t = threadIdx.x;
    const int w = t >> 5, ln = t & 31;
    __shared__ float red[8];

    float v[8];
    float m = -INFINITY;
#pragma unroll
    for (int i = 0; i < 8; i++) {
        v[i] = p[t + i * 256];
        m = fmaxf(m, v[i]);
    }
#pragma unroll
    for (int s = 16; s > 0; s >>= 1)
        m = fmaxf(m, __shfl_xor_sync(0xFFFFFFFFu, m, s));
    if (ln == 0) red[w] = m;
    __syncthreads();
    m = red[ln & 7];
#pragma unroll
    for (int s = 4; s > 0; s >>= 1)
        m = fmaxf(m, __shfl_xor_sync(0xFFFFFFFFu, m, s));

    float sum = 0.0f;
#pragma unroll
    for (int i = 0; i < 8; i++) {
        v[i] = __expf(v[i] - m);
        sum += v[i];
    }
#pragma unroll
    for (int s = 16; s > 0; s >>= 1)
        sum += __shfl_xor_sync(0xFFFFFFFFu, sum, s);
    __syncthreads();
    if (ln == 0) red[w] = sum;
    __syncthreads();
    sum = red[ln & 7];
#pragma unroll
    for (int s = 4; s > 0; s >>= 1)
        sum += __shfl_xor_sync(0xFFFFFFFFu, sum, s);

    const float inv = 1.0f / sum;
#pragma unroll
    for (int i = 0; i < 8; i++) {
        float val = v[i] * inv;
        p[t + i * 256] = val;
        ph[t + i * 256] = h16(val);
    }
}

// ---------------------------------------------------------------------------
extern "C" void kernel_launch(void* const* d_in, const int* in_sizes, int n_in,
                              void* d_out, int out_size)
{
    const float* x  = (const float*)d_in[0];
    const float* en = (const float*)d_in[1];
    const float* Wq = (const float*)d_in[2];
    const float* bq = (const float*)d_in[3];
    const float* Wf = (const float*)d_in[4];
    const float* bf = (const float*)d_in[5];

    float* out  = (float*)d_out;
    float* proj = out;
    float* att  = out + PROJ_ELEMS;

    auto sym = [](const void* s) {
        void* p = nullptr;
        cudaGetSymbolAddress(&p, s);
        return p;
    };
    uint16_t* xh   = (uint16_t*)sym(g_xh);
    uint16_t* xl   = (uint16_t*)sym(g_xl);
    uint16_t* wqT  = (uint16_t*)sym(g_wqT);
    uint16_t* enS  = (uint16_t*)sym(g_enS);
    uint16_t* enT  = (uint16_t*)sym(g_enT);
    uint16_t* wfT  = (uint16_t*)sym(g_wfT);
    float*    qf   = (float*)   sym(g_q);
    uint16_t* qh   = (uint16_t*)sym(g_qh);
    uint16_t* ql   = (uint16_t*)sym(g_ql);
    uint16_t* attH = (uint16_t*)sym(g_attH);
    uint16_t* sumh = (uint16_t*)sym(g_sumh);

    constexpr int SMEM3 = 2 * 3 * TILEB;   // 61440 (2-pass)
    constexpr int SMEM2 = 2 * 2 * TILEB;   // 40960 (1-pass)
    cudaFuncSetAttribute(mma_gemm<41, 2>, cudaFuncAttributeMaxDynamicSharedMemorySize, SMEM3);
    cudaFuncSetAttribute(mma_gemm<10, 2>, cudaFuncAttributeMaxDynamicSharedMemorySize, SMEM3);
    cudaFuncSetAttribute(mma_gemm<20, 1>, cudaFuncAttributeMaxDynamicSharedMemorySize, SMEM2);
    cudaFuncSetAttribute(mma_gemm<9,  1>, cudaFuncAttributeMaxDynamicSharedMemorySize, SMEM2);

    const float scale = 0.044194173824159216f;  // 1/sqrt(512)

    // --- pre-passes ---
    {
        long n4 = (long)BATCH * SQ * DIN / 4;
        split_plain_f16<<<(unsigned)((n4 + 255) / 256), 256>>>(x, xh, xl, n4);
    }
    conv_en_fused<<<dim3(DEMB / 32, SKV / 32, BATCH), dim3(32, 8)>>>(en, enS, enT);
    conv_T_f16<<<dim3(DEMB / 32, DIN / 32, 1), dim3(32, 8)>>>(Wq, wqT, DIN, DEMB);
    conv_T_f16<<<dim3(DOUT / 32, DEMB / 32, 1), dim3(32, 8)>>>(Wf, wfT, DEMB, DOUT);

    // 1) q = x @ wqT^T + bq    2-pass; writes q fp32 + fp16 hi/lo. MODE=1|8|32=41
    mma_gemm<41, 2><<<dim3(DEMB / 128, (BATCH * SQ) / 128, 1), 256, SMEM3>>>(
        xh, xl, wqT, qf, qh, ql, bq,
        BATCH * SQ, DEMB, DIN, 0, 0, 0, 0, 0.0f);

    // 2) scores = q @ enS^T * scale    2-pass; fp32 att. MODE=2|8=10
    mma_gemm<10, 2><<<dim3(SKV / 128, SQ / 128, BATCH), 256, SMEM3>>>(
        qh, ql, enS, att, nullptr, nullptr, nullptr,
        SQ, SKV, DEMB,
        (long)SQ * DEMB, (long)SKV * DEMB, (long)SQ * SKV, 0, scale);

    // 3) softmax in-place fp32 + fp16 copy
    softmax_rows<<<BATCH * SQ, 256>>>(att, attH);

    // 4) sum = attH @ enT^T + q    1-pass; fp16 sum out. MODE=4|16=20
    mma_gemm<20, 1><<<dim3(DEMB / 128, SQ / 128, BATCH), 256, SMEM2>>>(
        attH, nullptr, enT, nullptr, sumh, nullptr, qf,
        SQ, DEMB, SKV,
        (long)SQ * SKV, (long)DEMB * SKV, (long)SQ * DEMB, (long)SQ * DEMB, 0.0f);

    // 5) proj = sumh @ wfT^T + bf    1-pass; fp32 out. MODE=1|8=9
    mma_gemm<9, 1><<<dim3(DOUT / 128, (BATCH * SQ) / 128, 1), 256, SMEM2>>>(
        sumh, nullptr, wfT, proj, nullptr, nullptr, bf,
        BATCH * SQ, DOUT, DEMB, 0, 0, 0, 0, 0.0f);

    (void)in_sizes; (void)n_in; (void)out_size;
}

// round 9
// speedup vs baseline: 4.7794x; 1.1521x over previous
#include <cuda_runtime.h>
#include <cuda_fp16.h>
#include <math.h>
#include <stdint.h>

// ---------------------------------------------------------------------------
// Problem constants
// ---------------------------------------------------------------------------
constexpr int BATCH = 8;
constexpr int SQ    = 2048;
constexpr int SKV   = 2048;
constexpr int DIN   = 1024;
constexpr int DEMB  = 512;
constexpr int DOUT  = 512;

constexpr long PROJ_ELEMS = (long)BATCH * SQ * DOUT;

// ---------------------------------------------------------------------------
// Scratch (device globals; no allocation allowed)
// ---------------------------------------------------------------------------
__device__ __align__(16) uint16_t g_xh  [(long)BATCH * SQ * DIN];    // fp16 hi
__device__ __align__(16) uint16_t g_xl  [(long)BATCH * SQ * DIN];    // fp16 lo
__device__ __align__(16) uint16_t g_wqT [DEMB * DIN];                // fp16
__device__ __align__(16) uint16_t g_enS [(long)BATCH * SKV * DEMB];  // fp16, K-major
__device__ __align__(16) uint16_t g_enT [(long)BATCH * DEMB * SKV];  // fp16, transposed
__device__ __align__(16) uint16_t g_wfT [DOUT * DEMB];               // fp16
__device__ __align__(16) float    g_q   [(long)BATCH * SQ * DEMB];   // fp32 (residual)
__device__ __align__(16) uint16_t g_qh  [(long)BATCH * SQ * DEMB];   // fp16 single
__device__ __align__(16) uint16_t g_attH[(long)BATCH * SQ * SKV];    // fp16 att (post-softmax)
__device__ __align__(16) uint16_t g_sumh[(long)BATCH * SQ * DEMB];   // fp16 sum

// ---------------------------------------------------------------------------
// PTX helpers (sm_80-compatible path: mma.sync / ldmatrix / cp.async)
// ---------------------------------------------------------------------------
__device__ __forceinline__ uint32_t smem_u32(const void* p) {
    uint32_t a;
    asm("{ .reg .u64 t; cvta.to.shared.u64 t, %1; cvt.u32.u64 %0, t; }" : "=r"(a) : "l"(p));
    return a;
}

#define CP_ASYNC16(dst, src) \
    asm volatile("cp.async.cg.shared.global [%0], [%1], 16;" :: "r"(dst), "l"(src))
#define CP_COMMIT()  asm volatile("cp.async.commit_group;" ::: "memory")
#define CP_WAIT0()   asm volatile("cp.async.wait_group 0;" ::: "memory")
#define CP_WAIT1()   asm volatile("cp.async.wait_group 1;" ::: "memory")

#define LDSM_X4(r0, r1, r2, r3, addr) \
    asm volatile("ldmatrix.sync.aligned.m8n8.x4.shared.b16 {%0,%1,%2,%3}, [%4];" \
                 : "=r"(r0), "=r"(r1), "=r"(r2), "=r"(r3) : "r"(addr))

__device__ __forceinline__ void mma_h(float* d, const uint32_t* a, uint32_t b0, uint32_t b1) {
    asm volatile("mma.sync.aligned.m16n8k16.row.col.f32.f16.f16.f32 "
                 "{%0,%1,%2,%3}, {%4,%5,%6,%7}, {%8,%9}, {%0,%1,%2,%3};"
                 : "+f"(d[0]), "+f"(d[1]), "+f"(d[2]), "+f"(d[3])
                 : "r"(a[0]), "r"(a[1]), "r"(a[2]), "r"(a[3]), "r"(b0), "r"(b1));
}

// ---------------------------------------------------------------------------
// split helpers
// ---------------------------------------------------------------------------
__device__ __forceinline__ void split_h(float v, uint16_t& h, uint16_t& l) {
    __half hh = __float2half_rn(v);
    __half ll = __float2half_rn(v - __half2float(hh));
    h = __half_as_ushort(hh);
    l = __half_as_ushort(ll);
}
__device__ __forceinline__ uint32_t pk(uint16_t a, uint16_t b) {
    return (uint32_t)a | ((uint32_t)b << 16);
}
__device__ __forceinline__ uint16_t h16(float v) {
    return __half_as_ushort(__float2half_rn(v));
}

// ---------------------------------------------------------------------------
// Pre-pass kernels
// ---------------------------------------------------------------------------
__global__ void __launch_bounds__(256)
split_plain_f16(const float* __restrict__ src, uint16_t* __restrict__ hi,
                uint16_t* __restrict__ lo, long n4)
{
    long i = (long)blockIdx.x * 256 + threadIdx.x;
    if (i >= n4) return;
    float4 v = reinterpret_cast<const float4*>(src)[i];
    uint16_t h0,l0,h1,l1,h2,l2,h3,l3;
    split_h(v.x,h0,l0); split_h(v.y,h1,l1);
    split_h(v.z,h2,l2); split_h(v.w,h3,l3);
    reinterpret_cast<uint2*>(hi)[i] = make_uint2(pk(h0,h1), pk(h2,h3));
    reinterpret_cast<uint2*>(lo)[i] = make_uint2(pk(l0,l1), pk(l2,l3));
}

// en -> fp16 single (same layout) + fp16 single transposed [DEMB, SKV]
__global__ void __launch_bounds__(256)
conv_en_fused(const float* __restrict__ en, uint16_t* __restrict__ eS,
              uint16_t* __restrict__ eT)
{
    const long z = blockIdx.z;
    en += z * (long)SKV * DEMB;
    eS += z * (long)SKV * DEMB;
    eT += z * (long)DEMB * SKV;
    __shared__ float t[32][33];
    const int c0 = blockIdx.x * 32;   // DEMB
    const int r0 = blockIdx.y * 32;   // SKV
    const int tx = threadIdx.x, ty = threadIdx.y;
#pragma unroll
    for (int j = 0; j < 4; j++) {
        int r = r0 + ty + j * 8;
        float v = en[(long)r * DEMB + c0 + tx];
        t[ty + j * 8][tx] = v;
        eS[(long)r * DEMB + c0 + tx] = h16(v);
    }
    __syncthreads();
#pragma unroll
    for (int j = 0; j < 4; j++) {
        int c = c0 + ty + j * 8;
        eT[(long)c * SKV + r0 + tx] = h16(t[tx][ty + j * 8]);
    }
}

// W [R,C] fp32 -> WT [C,R] fp16 single
__global__ void __launch_bounds__(256)
conv_T_f16(const float* __restrict__ src, uint16_t* __restrict__ dstT, int R, int C)
{
    __shared__ float t[32][33];
    const int c0 = blockIdx.x * 32;
    const int r0 = blockIdx.y * 32;
    const int tx = threadIdx.x, ty = threadIdx.y;
#pragma unroll
    for (int j = 0; j < 4; j++) {
        int r = r0 + ty + j * 8;
        t[ty + j * 8][tx] = src[(long)r * C + c0 + tx];
    }
    __syncthreads();
#pragma unroll
    for (int j = 0; j < 4; j++) {
        int c = c0 + ty + j * 8;
        dstT[(long)c * R + r0 + tx] = h16(t[tx][ty + j * 8]);
    }
}

// ---------------------------------------------------------------------------
// fp16 HMMA GEMM: C[M,N] = A[M,K] @ B[N,K]^T (+epilogue)
// PASSES=2: A as (hi, lo) fp16 pair, 3 SMEM tiles/stage.
// PASSES=1: A single fp16, 2 SMEM tiles/stage.
// MODE bits: 1=bias, 2=scale, 4=residual, 8=write fp32, 16=write fp16 single
// ---------------------------------------------------------------------------
constexpr int ROWB  = 80;             // padded row bytes (32 elems * 2B = 64B data)
constexpr int TILEB = 128 * ROWB;     // 10240 B

template <int MODE, int PASSES>
__global__ void __launch_bounds__(256, 2)
mma_gemm(const uint16_t* __restrict__ Ah, const uint16_t* __restrict__ Al,
         const uint16_t* __restrict__ Bs,
         float* __restrict__ Cf, uint16_t* __restrict__ Ch,
         const float* __restrict__ aux,
         int M, int N, int K, long sA, long sB, long sC, long sAux, float scale)
{
    constexpr bool HAS_BIAS  = (MODE & 1)  != 0;
    constexpr bool HAS_SCALE = (MODE & 2)  != 0;
    constexpr bool HAS_RES   = (MODE & 4)  != 0;
    constexpr bool WR_F32    = (MODE & 8)  != 0;
    constexpr bool WR_F16    = (MODE & 16) != 0;
    constexpr int  NT        = PASSES + 1;    // tiles per stage
    constexpr int  BT        = NT - 1;        // B tile index

    extern __shared__ __align__(128) char dsm[];
    const uint32_t sbase = smem_u32(dsm);
    #define TILE(s, t) (sbase + ((s) * NT + (t)) * TILEB)

    const int tid  = threadIdx.x;
    const int wid  = tid >> 5;
    const int lane = tid & 31;

    const long z = blockIdx.z;
    Ah += z * sA;
    if (PASSES == 2) Al += z * sA;
    Bs += z * sB;
    const long cOff = z * sC;

    const int m0 = blockIdx.y * 128;
    const int n0 = blockIdx.x * 128;

    const int lrow = tid >> 2;           // 0..63
    const int lkg  = tid & 3;            // 16B group
    auto load_chunk = [&](int s, int k0) {
        {
            const uint16_t* g = Ah + (long)m0 * K + k0;
            const uint32_t st = TILE(s, 0);
#pragma unroll
            for (int h = 0; h < 2; h++) {
                int row = lrow + h * 64;
                CP_ASYNC16(st + row * ROWB + lkg * 16, g + (long)row * K + lkg * 8);
            }
        }
        if (PASSES == 2) {
            const uint16_t* g = Al + (long)m0 * K + k0;
            const uint32_t st = TILE(s, 1);
#pragma unroll
            for (int h = 0; h < 2; h++) {
                int row = lrow + h * 64;
                CP_ASYNC16(st + row * ROWB + lkg * 16, g + (long)row * K + lkg * 8);
            }
        }
        {
            const uint16_t* g = Bs + (long)n0 * K + k0;
            const uint32_t st = TILE(s, BT);
#pragma unroll
            for (int h = 0; h < 2; h++) {
                int row = lrow + h * 64;
                CP_ASYNC16(st + row * ROWB + lkg * 16, g + (long)row * K + lkg * 8);
            }
        }
    };

    float acc[4][4][4];
#pragma unroll
    for (int a = 0; a < 4; a++)
#pragma unroll
        for (int b = 0; b < 4; b++)
#pragma unroll
            for (int c = 0; c < 4; c++) acc[a][b][c] = 0.0f;

    const int nch = K >> 5;

    load_chunk(0, 0);
    CP_COMMIT();

    // warp layout: 2 (m) x 4 (n); warp tile 64x32
    const int m0w = (wid & 1) * 64;
    const int n0w = (wid >> 1) * 32;
    const int a_r = lane & 15;
    const int a_h = lane >> 4;
    const int b_r = lane & 7;
    const int b_q = lane >> 3;

    for (int i = 0; i < nch; i++) {
        const int s = i & 1;
        if (i + 1 < nch) {
            load_chunk(s ^ 1, (i + 1) * 32);
            CP_COMMIT();
            CP_WAIT1();
        } else {
            CP_WAIT0();
        }
        __syncthreads();

        const uint32_t Abh = TILE(s, 0);
        const uint32_t Abl = (PASSES == 2) ? TILE(s, 1) : 0;
        const uint32_t Bb  = TILE(s, BT);

#pragma unroll
        for (int ks = 0; ks < 2; ks++) {
            const int koff = ks * 32;
            uint32_t bh[8];
#pragma unroll
            for (int j = 0; j < 2; j++) {
                uint32_t boff = (uint32_t)((n0w + j * 16 + (b_q >> 1) * 8 + b_r) * ROWB
                                           + koff + (b_q & 1) * 16);
                LDSM_X4(bh[j*4+0], bh[j*4+1], bh[j*4+2], bh[j*4+3], Bb + boff);
            }
#pragma unroll
            for (int mi = 0; mi < 4; mi++) {
                uint32_t aoff = (uint32_t)((m0w + mi * 16 + a_r) * ROWB + koff + a_h * 16);
                uint32_t ahr[4];
                LDSM_X4(ahr[0], ahr[1], ahr[2], ahr[3], Abh + aoff);
#pragma unroll
                for (int ni = 0; ni < 4; ni++)
                    mma_h(acc[mi][ni], ahr, bh[ni*2], bh[ni*2+1]);
                if (PASSES == 2) {
                    uint32_t alr[4];
                    LDSM_X4(alr[0], alr[1], alr[2], alr[3], Abl + aoff);
#pragma unroll
                    for (int ni = 0; ni < 4; ni++)
                        mma_h(acc[mi][ni], alr, bh[ni*2], bh[ni*2+1]);
                }
            }
        }
        __syncthreads();
    }

    // ---- epilogue ----
    const float* auxp = aux;
    if (HAS_RES) auxp += z * sAux;
    const int crow = lane >> 2;
    const int ccol = (lane & 3) * 2;
#pragma unroll
    for (int mi = 0; mi < 4; mi++) {
#pragma unroll
        for (int rh = 0; rh < 2; rh++) {
            const long row = m0 + m0w + mi * 16 + crow + rh * 8;
#pragma unroll
            for (int ni = 0; ni < 4; ni++) {
                const int col = n0 + n0w + ni * 8 + ccol;
                float v0 = acc[mi][ni][rh * 2];
                float v1 = acc[mi][ni][rh * 2 + 1];
                if (HAS_BIAS)  { v0 += aux[col]; v1 += aux[col + 1]; }
                if (HAS_SCALE) { v0 *= scale; v1 *= scale; }
                if (HAS_RES)   {
                    v0 += auxp[row * (long)N + col];
                    v1 += auxp[row * (long)N + col + 1];
                }
                if (WR_F32)
                    *reinterpret_cast<float2*>(Cf + cOff + row * (long)N + col) =
                        make_float2(v0, v1);
                if (WR_F16)
                    *reinterpret_cast<uint32_t*>(Ch + cOff + row * (long)N + col) =
                        pk(h16(v0), h16(v1));
            }
        }
    }
    #undef TILE
}

// ---------------------------------------------------------------------------
// In-place fp32 row softmax over 2048 columns + fp16 copy for the A*V GEMM.
// ---------------------------------------------------------------------------
__global__ void __launch_bounds__(256)
softmax_rows(float* __restrict__ att, uint16_t* __restrict__ attH)
{
    const long row = blockIdx.x;
    float* p = att + row * (long)SKV;
    uint16_t* ph = attH + row * (long)SKV;
    const int t = threadIdx.x;
    const int w = t >> 5, ln = t & 31;
    __shared__ float red[8];

    float v[8];
    float m = -INFINITY;
#pragma unroll
    for (int i = 0; i < 8; i++) {
        v[i] = p[t + i * 256];
        m = fmaxf(m, v[i]);
    }
#pragma unroll
    for (int s = 16; s > 0; s >>= 1)
        m = fmaxf(m, __shfl_xor_sync(0xFFFFFFFFu, m, s));
    if (ln == 0) red[w] = m;
    __syncthreads();
    m = red[ln & 7];
#pragma unroll
    for (int s = 4; s > 0; s >>= 1)
        m = fmaxf(m, __shfl_xor_sync(0xFFFFFFFFu, m, s));

    float sum = 0.0f;
#pragma unroll
    for (int i = 0; i < 8; i++) {
        v[i] = __expf(v[i] - m);
        sum += v[i];
    }
#pragma unroll
    for (int s = 16; s > 0; s >>= 1)
        sum += __shfl_xor_sync(0xFFFFFFFFu, sum, s);
    __syncthreads();
    if (ln == 0) red[w] = sum;
    __syncthreads();
    sum = red[ln & 7];
#pragma unroll
    for (int s = 4; s > 0; s >>= 1)
        sum += __shfl_xor_sync(0xFFFFFFFFu, sum, s);

    const float inv = 1.0f / sum;
#pragma unroll
    for (int i = 0; i < 8; i++) {
        float val = v[i] * inv;
        p[t + i * 256] = val;
        ph[t + i * 256] = h16(val);
    }
}

// ---------------------------------------------------------------------------
extern "C" void kernel_launch(void* const* d_in, const int* in_sizes, int n_in,
                              void* d_out, int out_size)
{
    const float* x  = (const float*)d_in[0];
    const float* en = (const float*)d_in[1];
    const float* Wq = (const float*)d_in[2];
    const float* bq = (const float*)d_in[3];
    const float* Wf = (const float*)d_in[4];
    const float* bf = (const float*)d_in[5];

    float* out  = (float*)d_out;
    float* proj = out;
    float* att  = out + PROJ_ELEMS;

    auto sym = [](const void* s) {
        void* p = nullptr;
        cudaGetSymbolAddress(&p, s);
        return p;
    };
    uint16_t* xh   = (uint16_t*)sym(g_xh);
    uint16_t* xl   = (uint16_t*)sym(g_xl);
    uint16_t* wqT  = (uint16_t*)sym(g_wqT);
    uint16_t* enS  = (uint16_t*)sym(g_enS);
    uint16_t* enT  = (uint16_t*)sym(g_enT);
    uint16_t* wfT  = (uint16_t*)sym(g_wfT);
    float*    qf   = (float*)   sym(g_q);
    uint16_t* qh   = (uint16_t*)sym(g_qh);
    uint16_t* attH = (uint16_t*)sym(g_attH);
    uint16_t* sumh = (uint16_t*)sym(g_sumh);

    constexpr int SMEM3 = 2 * 3 * TILEB;   // 61440 (2-pass)
    constexpr int SMEM2 = 2 * 2 * TILEB;   // 40960 (1-pass)
    cudaFuncSetAttribute(mma_gemm<25, 2>, cudaFuncAttributeMaxDynamicSharedMemorySize, SMEM3);
    cudaFuncSetAttribute(mma_gemm<10, 1>, cudaFuncAttributeMaxDynamicSharedMemorySize, SMEM2);
    cudaFuncSetAttribute(mma_gemm<20, 1>, cudaFuncAttributeMaxDynamicSharedMemorySize, SMEM2);
    cudaFuncSetAttribute(mma_gemm<9,  1>, cudaFuncAttributeMaxDynamicSharedMemorySize, SMEM2);

    const float scale = 0.044194173824159216f;  // 1/sqrt(512)

    // --- pre-passes ---
    {
        long n4 = (long)BATCH * SQ * DIN / 4;
        split_plain_f16<<<(unsigned)((n4 + 255) / 256), 256>>>(x, xh, xl, n4);
    }
    conv_en_fused<<<dim3(DEMB / 32, SKV / 32, BATCH), dim3(32, 8)>>>(en, enS, enT);
    conv_T_f16<<<dim3(DEMB / 32, DIN / 32, 1), dim3(32, 8)>>>(Wq, wqT, DIN, DEMB);
    conv_T_f16<<<dim3(DOUT / 32, DEMB / 32, 1), dim3(32, 8)>>>(Wf, wfT, DEMB, DOUT);

    // 1) q = x @ wqT^T + bq    2-pass; writes q fp32 + fp16 single. MODE=1|8|16=25
    mma_gemm<25, 2><<<dim3(DEMB / 128, (BATCH * SQ) / 128, 1), 256, SMEM3>>>(
        xh, xl, wqT, qf, qh, bq,
        BATCH * SQ, DEMB, DIN, 0, 0, 0, 0, 0.0f);

    // 2) scores = q @ enS^T * scale    1-pass; fp32 att. MODE=2|8=10
    mma_gemm<10, 1><<<dim3(SKV / 128, SQ / 128, BATCH), 256, SMEM2>>>(
        qh, nullptr, enS, att, nullptr, nullptr,
        SQ, SKV, DEMB,
        (long)SQ * DEMB, (long)SKV * DEMB, (long)SQ * SKV, 0, scale);

    // 3) softmax in-place fp32 + fp16 copy
    softmax_rows<<<BATCH * SQ, 256>>>(att, attH);

    // 4) sum = attH @ enT^T + q    1-pass; fp16 sum out. MODE=4|16=20
    mma_gemm<20, 1><<<dim3(DEMB / 128, SQ / 128, BATCH), 256, SMEM2>>>(
        attH, nullptr, enT, nullptr, sumh, qf,
        SQ, DEMB, SKV,
        (long)SQ * SKV, (long)DEMB * SKV, (long)SQ * DEMB, (long)SQ * DEMB, 0.0f);

    // 5) proj = sumh @ wfT^T + bf    1-pass; fp32 out. MODE=1|8=9
    mma_gemm<9, 1><<<dim3(DOUT / 128, (BATCH * SQ) / 128, 1), 256, SMEM2>>>(
        sumh, nullptr, wfT, proj, nullptr, bf,
        BATCH * SQ, DOUT, DEMB, 0, 0, 0, 0, 0.0f);

    (void)in_sizes; (void)n_in; (void)out_size;
}

// round 11
// speedup vs baseline: 5.2590x; 1.1004x over previous
#include <cuda_runtime.h>
#include <cuda_fp16.h>
#include <math.h>
#include <stdint.h>

// ---------------------------------------------------------------------------
// Problem constants
// ---------------------------------------------------------------------------
constexpr int BATCH = 8;
constexpr int SQ    = 2048;
constexpr int SKV   = 2048;
constexpr int DIN   = 1024;
constexpr int DEMB  = 512;
constexpr int DOUT  = 512;

constexpr long PROJ_ELEMS = (long)BATCH * SQ * DOUT;

// ---------------------------------------------------------------------------
// Scratch (device globals; no allocation allowed)
// ---------------------------------------------------------------------------
__device__ __align__(16) uint16_t g_xh  [(long)BATCH * SQ * DIN];    // fp16
__device__ __align__(16) uint16_t g_wqT [DEMB * DIN];                // fp16
__device__ __align__(16) uint16_t g_enS [(long)BATCH * SKV * DEMB];  // fp16, K-major
__device__ __align__(16) uint16_t g_enT [(long)BATCH * DEMB * SKV];  // fp16, transposed
__device__ __align__(16) uint16_t g_wfT [DOUT * DEMB];               // fp16
__device__ __align__(16) float    g_q   [(long)BATCH * SQ * DEMB];   // fp32 (residual)
__device__ __align__(16) uint16_t g_qh  [(long)BATCH * SQ * DEMB];   // fp16 single
__device__ __align__(16) uint16_t g_attH[(long)BATCH * SQ * SKV];    // fp16 att (post-softmax)
__device__ __align__(16) uint16_t g_sumh[(long)BATCH * SQ * DEMB];   // fp16 sum

// ---------------------------------------------------------------------------
// PTX helpers (sm_80-compatible path: mma.sync / ldmatrix / cp.async)
// ---------------------------------------------------------------------------
__device__ __forceinline__ uint32_t smem_u32(const void* p) {
    uint32_t a;
    asm("{ .reg .u64 t; cvta.to.shared.u64 t, %1; cvt.u32.u64 %0, t; }" : "=r"(a) : "l"(p));
    return a;
}

#define CP_ASYNC16(dst, src) \
    asm volatile("cp.async.cg.shared.global [%0], [%1], 16;" :: "r"(dst), "l"(src))
#define CP_COMMIT()  asm volatile("cp.async.commit_group;" ::: "memory")
#define CP_WAIT0()   asm volatile("cp.async.wait_group 0;" ::: "memory")
#define CP_WAIT1()   asm volatile("cp.async.wait_group 1;" ::: "memory")

#define LDSM_X4(r0, r1, r2, r3, addr) \
    asm volatile("ldmatrix.sync.aligned.m8n8.x4.shared.b16 {%0,%1,%2,%3}, [%4];" \
                 : "=r"(r0), "=r"(r1), "=r"(r2), "=r"(r3) : "r"(addr))

__device__ __forceinline__ void mma_h(float* d, const uint32_t* a, uint32_t b0, uint32_t b1) {
    asm volatile("mma.sync.aligned.m16n8k16.row.col.f32.f16.f16.f32 "
                 "{%0,%1,%2,%3}, {%4,%5,%6,%7}, {%8,%9}, {%0,%1,%2,%3};"
                 : "+f"(d[0]), "+f"(d[1]), "+f"(d[2]), "+f"(d[3])
                 : "r"(a[0]), "r"(a[1]), "r"(a[2]), "r"(a[3]), "r"(b0), "r"(b1));
}

// ---------------------------------------------------------------------------
// helpers
// ---------------------------------------------------------------------------
__device__ __forceinline__ uint32_t pk(uint16_t a, uint16_t b) {
    return (uint32_t)a | ((uint32_t)b << 16);
}
__device__ __forceinline__ uint16_t h16(float v) {
    return __half_as_ushort(__float2half_rn(v));
}

// ---------------------------------------------------------------------------
// Pre-pass kernels
// ---------------------------------------------------------------------------
// plain fp32 -> fp16 convert
__global__ void __launch_bounds__(256)
conv_plain_f16(const float* __restrict__ src, uint16_t* __restrict__ dst, long n4)
{
    long i = (long)blockIdx.x * 256 + threadIdx.x;
    if (i >= n4) return;
    float4 v = reinterpret_cast<const float4*>(src)[i];
    reinterpret_cast<uint2*>(dst)[i] =
        make_uint2(pk(h16(v.x), h16(v.y)), pk(h16(v.z), h16(v.w)));
}

// en -> fp16 single (same layout) + fp16 single transposed [DEMB, SKV]
__global__ void __launch_bounds__(256)
conv_en_fused(const float* __restrict__ en, uint16_t* __restrict__ eS,
              uint16_t* __restrict__ eT)
{
    const long z = blockIdx.z;
    en += z * (long)SKV * DEMB;
    eS += z * (long)SKV * DEMB;
    eT += z * (long)DEMB * SKV;
    __shared__ float t[32][33];
    const int c0 = blockIdx.x * 32;   // DEMB
    const int r0 = blockIdx.y * 32;   // SKV
    const int tx = threadIdx.x, ty = threadIdx.y;
#pragma unroll
    for (int j = 0; j < 4; j++) {
        int r = r0 + ty + j * 8;
        float v = en[(long)r * DEMB + c0 + tx];
        t[ty + j * 8][tx] = v;
        eS[(long)r * DEMB + c0 + tx] = h16(v);
    }
    __syncthreads();
#pragma unroll
    for (int j = 0; j < 4; j++) {
        int c = c0 + ty + j * 8;
        eT[(long)c * SKV + r0 + tx] = h16(t[tx][ty + j * 8]);
    }
}

// W [R,C] fp32 -> WT [C,R] fp16 single
__global__ void __launch_bounds__(256)
conv_T_f16(const float* __restrict__ src, uint16_t* __restrict__ dstT, int R, int C)
{
    __shared__ float t[32][33];
    const int c0 = blockIdx.x * 32;
    const int r0 = blockIdx.y * 32;
    const int tx = threadIdx.x, ty = threadIdx.y;
#pragma unroll
    for (int j = 0; j < 4; j++) {
        int r = r0 + ty + j * 8;
        t[ty + j * 8][tx] = src[(long)r * C + c0 + tx];
    }
    __syncthreads();
#pragma unroll
    for (int j = 0; j < 4; j++) {
        int c = c0 + ty + j * 8;
        dstT[(long)c * R + r0 + tx] = h16(t[tx][ty + j * 8]);
    }
}

// ---------------------------------------------------------------------------
// fp16 HMMA GEMM: C[M,N] = A[M,K] @ B[N,K]^T (+epilogue)
// 1-pass fp16, 2 SMEM tiles per stage, cp.async double buffer,
// 8 warps of 64x32, mma.sync m16n8k16.
// MODE bits: 1=bias, 2=scale, 4=residual, 8=write fp32, 16=write fp16 single
// ---------------------------------------------------------------------------
constexpr int ROWB  = 80;             // padded row bytes (32 elems * 2B = 64B data)
constexpr int TILEB = 128 * ROWB;     // 10240 B
constexpr int SMEM_BYTES = 2 * 2 * TILEB;  // 40960

template <int MODE>
__global__ void __launch_bounds__(256, 2)
mma_gemm(const uint16_t* __restrict__ Ah, const uint16_t* __restrict__ Bs,
         float* __restrict__ Cf, uint16_t* __restrict__ Ch,
         const float* __restrict__ aux,
         int M, int N, int K, long sA, long sB, long sC, long sAux, float scale)
{
    constexpr bool HAS_BIAS  = (MODE & 1)  != 0;
    constexpr bool HAS_SCALE = (MODE & 2)  != 0;
    constexpr bool HAS_RES   = (MODE & 4)  != 0;
    constexpr bool WR_F32    = (MODE & 8)  != 0;
    constexpr bool WR_F16    = (MODE & 16) != 0;

    extern __shared__ __align__(128) char dsm[];
    const uint32_t sbase = smem_u32(dsm);
    #define TILE(s, t) (sbase + ((s) * 2 + (t)) * TILEB)

    const int tid  = threadIdx.x;
    const int wid  = tid >> 5;
    const int lane = tid & 31;

    const long z = blockIdx.z;
    Ah += z * sA;
    Bs += z * sB;
    const long cOff = z * sC;

    const int m0 = blockIdx.y * 128;
    const int n0 = blockIdx.x * 128;

    const int lrow = tid >> 2;           // 0..63
    const int lkg  = tid & 3;            // 16B group
    auto load_chunk = [&](int s, int k0) {
        {
            const uint16_t* g = Ah + (long)m0 * K + k0;
            const uint32_t st = TILE(s, 0);
#pragma unroll
            for (int h = 0; h < 2; h++) {
                int row = lrow + h * 64;
                CP_ASYNC16(st + row * ROWB + lkg * 16, g + (long)row * K + lkg * 8);
            }
        }
        {
            const uint16_t* g = Bs + (long)n0 * K + k0;
            const uint32_t st = TILE(s, 1);
#pragma unroll
            for (int h = 0; h < 2; h++) {
                int row = lrow + h * 64;
                CP_ASYNC16(st + row * ROWB + lkg * 16, g + (long)row * K + lkg * 8);
            }
        }
    };

    float acc[4][4][4];
#pragma unroll
    for (int a = 0; a < 4; a++)
#pragma unroll
        for (int b = 0; b < 4; b++)
#pragma unroll
            for (int c = 0; c < 4; c++) acc[a][b][c] = 0.0f;

    const int nch = K >> 5;

    load_chunk(0, 0);
    CP_COMMIT();

    // warp layout: 2 (m) x 4 (n); warp tile 64x32
    const int m0w = (wid & 1) * 64;
    const int n0w = (wid >> 1) * 32;
    const int a_r = lane & 15;
    const int a_h = lane >> 4;
    const int b_r = lane & 7;
    const int b_q = lane >> 3;

    for (int i = 0; i < nch; i++) {
        const int s = i & 1;
        if (i + 1 < nch) {
            load_chunk(s ^ 1, (i + 1) * 32);
            CP_COMMIT();
            CP_WAIT1();
        } else {
            CP_WAIT0();
        }
        __syncthreads();

        const uint32_t Ab = TILE(s, 0);
        const uint32_t Bb = TILE(s, 1);

#pragma unroll
        for (int ks = 0; ks < 2; ks++) {
            const int koff = ks * 32;
            uint32_t bh[8];
#pragma unroll
            for (int j = 0; j < 2; j++) {
                uint32_t boff = (uint32_t)((n0w + j * 16 + (b_q >> 1) * 8 + b_r) * ROWB
                                           + koff + (b_q & 1) * 16);
                LDSM_X4(bh[j*4+0], bh[j*4+1], bh[j*4+2], bh[j*4+3], Bb + boff);
            }
#pragma unroll
            for (int mi = 0; mi < 4; mi++) {
                uint32_t aoff = (uint32_t)((m0w + mi * 16 + a_r) * ROWB + koff + a_h * 16);
                uint32_t ahr[4];
                LDSM_X4(ahr[0], ahr[1], ahr[2], ahr[3], Ab + aoff);
#pragma unroll
                for (int ni = 0; ni < 4; ni++)
                    mma_h(acc[mi][ni], ahr, bh[ni*2], bh[ni*2+1]);
            }
        }
        __syncthreads();
    }

    // ---- epilogue ----
    const float* auxp = aux;
    if (HAS_RES) auxp += z * sAux;
    const int crow = lane >> 2;
    const int ccol = (lane & 3) * 2;
#pragma unroll
    for (int mi = 0; mi < 4; mi++) {
#pragma unroll
        for (int rh = 0; rh < 2; rh++) {
            const long row = m0 + m0w + mi * 16 + crow + rh * 8;
#pragma unroll
            for (int ni = 0; ni < 4; ni++) {
                const int col = n0 + n0w + ni * 8 + ccol;
                float v0 = acc[mi][ni][rh * 2];
                float v1 = acc[mi][ni][rh * 2 + 1];
                if (HAS_BIAS)  { v0 += aux[col]; v1 += aux[col + 1]; }
                if (HAS_SCALE) { v0 *= scale; v1 *= scale; }
                if (HAS_RES)   {
                    v0 += auxp[row * (long)N + col];
                    v1 += auxp[row * (long)N + col + 1];
                }
                if (WR_F32)
                    *reinterpret_cast<float2*>(Cf + cOff + row * (long)N + col) =
                        make_float2(v0, v1);
                if (WR_F16)
                    *reinterpret_cast<uint32_t*>(Ch + cOff + row * (long)N + col) =
                        pk(h16(v0), h16(v1));
            }
        }
    }
    #undef TILE
}

// ---------------------------------------------------------------------------
// In-place fp32 row softmax over 2048 columns + fp16 copy for the A*V GEMM.
// ---------------------------------------------------------------------------
__global__ void __launch_bounds__(256)
softmax_rows(float* __restrict__ att, uint16_t* __restrict__ attH)
{
    const long row = blockIdx.x;
    float* p = att + row * (long)SKV;
    uint16_t* ph = attH + row * (long)SKV;
    const int t = threadIdx.x;
    const int w = t >> 5, ln = t & 31;
    __shared__ float red[8];

    float v[8];
    float m = -INFINITY;
#pragma unroll
    for (int i = 0; i < 8; i++) {
        v[i] = p[t + i * 256];
        m = fmaxf(m, v[i]);
    }
#pragma unroll
    for (int s = 16; s > 0; s >>= 1)
        m = fmaxf(m, __shfl_xor_sync(0xFFFFFFFFu, m, s));
    if (ln == 0) red[w] = m;
    __syncthreads();
    m = red[ln & 7];
#pragma unroll
    for (int s = 4; s > 0; s >>= 1)
        m = fmaxf(m, __shfl_xor_sync(0xFFFFFFFFu, m, s));

    float sum = 0.0f;
#pragma unroll
    for (int i = 0; i < 8; i++) {
        v[i] = __expf(v[i] - m);
        sum += v[i];
    }
#pragma unroll
    for (int s = 16; s > 0; s >>= 1)
        sum += __shfl_xor_sync(0xFFFFFFFFu, sum, s);
    __syncthreads();
    if (ln == 0) red[w] = sum;
    __syncthreads();
    sum = red[ln & 7];
#pragma unroll
    for (int s = 4; s > 0; s >>= 1)
        sum += __shfl_xor_sync(0xFFFFFFFFu, sum, s);

    const float inv = 1.0f / sum;
#pragma unroll
    for (int i = 0; i < 8; i++) {
        float val = v[i] * inv;
        p[t + i * 256] = val;
        ph[t + i * 256] = h16(val);
    }
}

// ---------------------------------------------------------------------------
extern "C" void kernel_launch(void* const* d_in, const int* in_sizes, int n_in,
                              void* d_out, int out_size)
{
    const float* x  = (const float*)d_in[0];
    const float* en = (const float*)d_in[1];
    const float* Wq = (const float*)d_in[2];
    const float* bq = (const float*)d_in[3];
    const float* Wf = (const float*)d_in[4];
    const float* bf = (const float*)d_in[5];

    float* out  = (float*)d_out;
    float* proj = out;
    float* att  = out + PROJ_ELEMS;

    auto sym = [](const void* s) {
        void* p = nullptr;
        cudaGetSymbolAddress(&p, s);
        return p;
    };
    uint16_t* xh   = (uint16_t*)sym(g_xh);
    uint16_t* wqT  = (uint16_t*)sym(g_wqT);
    uint16_t* enS  = (uint16_t*)sym(g_enS);
    uint16_t* enT  = (uint16_t*)sym(g_enT);
    uint16_t* wfT  = (uint16_t*)sym(g_wfT);
    float*    qf   = (float*)   sym(g_q);
    uint16_t* qh   = (uint16_t*)sym(g_qh);
    uint16_t* attH = (uint16_t*)sym(g_attH);
    uint16_t* sumh = (uint16_t*)sym(g_sumh);

    cudaFuncSetAttribute(mma_gemm<25>, cudaFuncAttributeMaxDynamicSharedMemorySize, SMEM_BYTES);
    cudaFuncSetAttribute(mma_gemm<10>, cudaFuncAttributeMaxDynamicSharedMemorySize, SMEM_BYTES);
    cudaFuncSetAttribute(mma_gemm<20>, cudaFuncAttributeMaxDynamicSharedMemorySize, SMEM_BYTES);
    cudaFuncSetAttribute(mma_gemm<9>,  cudaFuncAttributeMaxDynamicSharedMemorySize, SMEM_BYTES);

    const float scale = 0.044194173824159216f;  // 1/sqrt(512)

    // --- pre-passes ---
    {
        long n4 = (long)BATCH * SQ * DIN / 4;
        conv_plain_f16<<<(unsigned)((n4 + 255) / 256), 256>>>(x, xh, n4);
    }
    conv_en_fused<<<dim3(DEMB / 32, SKV / 32, BATCH), dim3(32, 8)>>>(en, enS, enT);
    conv_T_f16<<<dim3(DEMB / 32, DIN / 32, 1), dim3(32, 8)>>>(Wq, wqT, DIN, DEMB);
    conv_T_f16<<<dim3(DOUT / 32, DEMB / 32, 1), dim3(32, 8)>>>(Wf, wfT, DEMB, DOUT);

    // 1) q = x @ wqT^T + bq    writes q fp32 + fp16 single. MODE=1|8|16=25
    mma_gemm<25><<<dim3(DEMB / 128, (BATCH * SQ) / 128, 1), 256, SMEM_BYTES>>>(
        xh, wqT, qf, qh, bq,
        BATCH * SQ, DEMB, DIN, 0, 0, 0, 0, 0.0f);

    // 2) scores = q @ enS^T * scale    fp32 att. MODE=2|8=10
    mma_gemm<10><<<dim3(SKV / 128, SQ / 128, BATCH), 256, SMEM_BYTES>>>(
        qh, enS, att, nullptr, nullptr,
        SQ, SKV, DEMB,
        (long)SQ * DEMB, (long)SKV * DEMB, (long)SQ * SKV, 0, scale);

    // 3) softmax in-place fp32 + fp16 copy
    softmax_rows<<<BATCH * SQ, 256>>>(att, attH);

    // 4) sum = attH @ enT^T + q    fp16 sum out. MODE=4|16=20
    mma_gemm<20><<<dim3(DEMB / 128, SQ / 128, BATCH), 256, SMEM_BYTES>>>(
        attH, enT, nullptr, sumh, qf,
        SQ, DEMB, SKV,
        (long)SQ * SKV, (long)DEMB * SKV, (long)SQ * DEMB, (long)SQ * DEMB, 0.0f);

    // 5) proj = sumh @ wfT^T + bf    fp32 out. MODE=1|8=9
    mma_gemm<9><<<dim3(DOUT / 128, (BATCH * SQ) / 128, 1), 256, SMEM_BYTES>>>(
        sumh, wfT, proj, nullptr, bf,
        BATCH * SQ, DOUT, DEMB, 0, 0, 0, 0, 0.0f);

    (void)in_sizes; (void)n_in; (void)out_size;
}

// round 13
// speedup vs baseline: 5.2594x; 1.0001x over previous
#include <cuda_runtime.h>
#include <cuda_fp16.h>
#include <math.h>
#include <stdint.h>

// ---------------------------------------------------------------------------
// Problem constants
// ---------------------------------------------------------------------------
constexpr int BATCH = 8;
constexpr int SQ    = 2048;
constexpr int SKV   = 2048;
constexpr int DIN   = 1024;
constexpr int DEMB  = 512;
constexpr int DOUT  = 512;

constexpr long PROJ_ELEMS = (long)BATCH * SQ * DOUT;

// ---------------------------------------------------------------------------
// Scratch (device globals; no allocation allowed)
// ---------------------------------------------------------------------------
__device__ __align__(16) uint16_t g_xh  [(long)BATCH * SQ * DIN];    // fp16
__device__ __align__(16) uint16_t g_wqT [DEMB * DIN];                // fp16
__device__ __align__(16) uint16_t g_enS [(long)BATCH * SKV * DEMB];  // fp16, K-major
__device__ __align__(16) uint16_t g_enT [(long)BATCH * DEMB * SKV];  // fp16, transposed
__device__ __align__(16) uint16_t g_wfT [DOUT * DEMB];               // fp16
__device__ __align__(16) float    g_q   [(long)BATCH * SQ * DEMB];   // fp32 (residual)
__device__ __align__(16) uint16_t g_qh  [(long)BATCH * SQ * DEMB];   // fp16 single
__device__ __align__(16) uint16_t g_attH[(long)BATCH * SQ * SKV];    // fp16 att (post-softmax)
__device__ __align__(16) uint16_t g_sumh[(long)BATCH * SQ * DEMB];   // fp16 sum

// ---------------------------------------------------------------------------
// PTX helpers (sm_80-compatible path: mma.sync / ldmatrix / cp.async)
// ---------------------------------------------------------------------------
__device__ __forceinline__ uint32_t smem_u32(const void* p) {
    uint32_t a;
    asm("{ .reg .u64 t; cvta.to.shared.u64 t, %1; cvt.u32.u64 %0, t; }" : "=r"(a) : "l"(p));
    return a;
}

#define CP_ASYNC16(dst, src) \
    asm volatile("cp.async.cg.shared.global [%0], [%1], 16;" :: "r"(dst), "l"(src))
#define CP_COMMIT()  asm volatile("cp.async.commit_group;" ::: "memory")
#define CP_WAIT0()   asm volatile("cp.async.wait_group 0;" ::: "memory")
#define CP_WAIT1()   asm volatile("cp.async.wait_group 1;" ::: "memory")
#define CP_WAIT2()   asm volatile("cp.async.wait_group 2;" ::: "memory")

#define LDSM_X4(r0, r1, r2, r3, addr) \
    asm volatile("ldmatrix.sync.aligned.m8n8.x4.shared.b16 {%0,%1,%2,%3}, [%4];" \
                 : "=r"(r0), "=r"(r1), "=r"(r2), "=r"(r3) : "r"(addr))

__device__ __forceinline__ void mma_h(float* d, const uint32_t* a, uint32_t b0, uint32_t b1) {
    asm volatile("mma.sync.aligned.m16n8k16.row.col.f32.f16.f16.f32 "
                 "{%0,%1,%2,%3}, {%4,%5,%6,%7}, {%8,%9}, {%0,%1,%2,%3};"
                 : "+f"(d[0]), "+f"(d[1]), "+f"(d[2]), "+f"(d[3])
                 : "r"(a[0]), "r"(a[1]), "r"(a[2]), "r"(a[3]), "r"(b0), "r"(b1));
}

// ---------------------------------------------------------------------------
// helpers
// ---------------------------------------------------------------------------
__device__ __forceinline__ uint32_t pk(uint16_t a, uint16_t b) {
    return (uint32_t)a | ((uint32_t)b << 16);
}
__device__ __forceinline__ uint16_t h16(float v) {
    return __half_as_ushort(__float2half_rn(v));
}

// ---------------------------------------------------------------------------
// Pre-pass kernels
// ---------------------------------------------------------------------------
// plain fp32 -> fp16 convert
__global__ void __launch_bounds__(256)
conv_plain_f16(const float* __restrict__ src, uint16_t* __restrict__ dst, long n4)
{
    long i = (long)blockIdx.x * 256 + threadIdx.x;
    if (i >= n4) return;
    float4 v = reinterpret_cast<const float4*>(src)[i];
    reinterpret_cast<uint2*>(dst)[i] =
        make_uint2(pk(h16(v.x), h16(v.y)), pk(h16(v.z), h16(v.w)));
}

// en -> fp16 single (same layout) + fp16 single transposed [DEMB, SKV]
__global__ void __launch_bounds__(256)
conv_en_fused(const float* __restrict__ en, uint16_t* __restrict__ eS,
              uint16_t* __restrict__ eT)
{
    const long z = blockIdx.z;
    en += z * (long)SKV * DEMB;
    eS += z * (long)SKV * DEMB;
    eT += z * (long)DEMB * SKV;
    __shared__ float t[32][33];
    const int c0 = blockIdx.x * 32;   // DEMB
    const int r0 = blockIdx.y * 32;   // SKV
    const int tx = threadIdx.x, ty = threadIdx.y;
#pragma unroll
    for (int j = 0; j < 4; j++) {
        int r = r0 + ty + j * 8;
        float v = en[(long)r * DEMB + c0 + tx];
        t[ty + j * 8][tx] = v;
        eS[(long)r * DEMB + c0 + tx] = h16(v);
    }
    __syncthreads();
#pragma unroll
    for (int j = 0; j < 4; j++) {
        int c = c0 + ty + j * 8;
        eT[(long)c * SKV + r0 + tx] = h16(t[tx][ty + j * 8]);
    }
}

// W [R,C] fp32 -> WT [C,R] fp16 single
__global__ void __launch_bounds__(256)
conv_T_f16(const float* __restrict__ src, uint16_t* __restrict__ dstT, int R, int C)
{
    __shared__ float t[32][33];
    const int c0 = blockIdx.x * 32;
    const int r0 = blockIdx.y * 32;
    const int tx = threadIdx.x, ty = threadIdx.y;
#pragma unroll
    for (int j = 0; j < 4; j++) {
        int r = r0 + ty + j * 8;
        t[ty + j * 8][tx] = src[(long)r * C + c0 + tx];
    }
    __syncthreads();
#pragma unroll
    for (int j = 0; j < 4; j++) {
        int c = c0 + ty + j * 8;
        dstT[(long)c * R + r0 + tx] = h16(t[tx][ty + j * 8]);
    }
}

// ---------------------------------------------------------------------------
// fp16 HMMA GEMM: C[M,N] = A[M,K] @ B[N,K]^T (+epilogue)
// 1-pass fp16, 3-stage cp.async pipeline (2 chunk-loads in flight),
// 2 SMEM tiles per stage, 8 warps of 64x32, mma.sync m16n8k16.
// MODE bits: 1=bias, 2=scale, 4=residual, 8=write fp32, 16=write fp16 single
// ---------------------------------------------------------------------------
constexpr int ROWB  = 80;             // padded row bytes (32 elems * 2B = 64B data)
constexpr int TILEB = 128 * ROWB;     // 10240 B
constexpr int STAGES = 3;
constexpr int SMEM_BYTES = STAGES * 2 * TILEB;  // 61440

template <int MODE>
__global__ void __launch_bounds__(256, 2)
mma_gemm(const uint16_t* __restrict__ Ah, const uint16_t* __restrict__ Bs,
         float* __restrict__ Cf, uint16_t* __restrict__ Ch,
         const float* __restrict__ aux,
         int M, int N, int K, long sA, long sB, long sC, long sAux, float scale)
{
    constexpr bool HAS_BIAS  = (MODE & 1)  != 0;
    constexpr bool HAS_SCALE = (MODE & 2)  != 0;
    constexpr bool HAS_RES   = (MODE & 4)  != 0;
    constexpr bool WR_F32    = (MODE & 8)  != 0;
    constexpr bool WR_F16    = (MODE & 16) != 0;

    extern __shared__ __align__(128) char dsm[];
    const uint32_t sbase = smem_u32(dsm);
    #define TILE(s, t) (sbase + ((s) * 2 + (t)) * TILEB)

    const int tid  = threadIdx.x;
    const int wid  = tid >> 5;
    const int lane = tid & 31;

    const long z = blockIdx.z;
    Ah += z * sA;
    Bs += z * sB;
    const long cOff = z * sC;

    const int m0 = blockIdx.y * 128;
    const int n0 = blockIdx.x * 128;

    const int lrow = tid >> 2;           // 0..63
    const int lkg  = tid & 3;            // 16B group
    auto load_chunk = [&](int s, int k0) {
        {
            const uint16_t* g = Ah + (long)m0 * K + k0;
            const uint32_t st = TILE(s, 0);
#pragma unroll
            for (int h = 0; h < 2; h++) {
                int row = lrow + h * 64;
                CP_ASYNC16(st + row * ROWB + lkg * 16, g + (long)row * K + lkg * 8);
            }
        }
        {
            const uint16_t* g = Bs + (long)n0 * K + k0;
            const uint32_t st = TILE(s, 1);
#pragma unroll
            for (int h = 0; h < 2; h++) {
                int row = lrow + h * 64;
                CP_ASYNC16(st + row * ROWB + lkg * 16, g + (long)row * K + lkg * 8);
            }
        }
    };

    float acc[4][4][4];
#pragma unroll
    for (int a = 0; a < 4; a++)
#pragma unroll
        for (int b = 0; b < 4; b++)
#pragma unroll
            for (int c = 0; c < 4; c++) acc[a][b][c] = 0.0f;

    const int nch = K >> 5;

    // prologue: 2 chunk-loads in flight
    load_chunk(0, 0);
    CP_COMMIT();
    if (nch > 1) {
        load_chunk(1, 32);
        CP_COMMIT();
    }

    // warp layout: 2 (m) x 4 (n); warp tile 64x32
    const int m0w = (wid & 1) * 64;
    const int n0w = (wid >> 1) * 32;
    const int a_r = lane & 15;
    const int a_h = lane >> 4;
    const int b_r = lane & 7;
    const int b_q = lane >> 3;

    for (int i = 0; i < nch; i++) {
        // issue load for chunk i+2 (stage reuse protected by the trailing
        // __syncthreads of iteration i-1)
        if (i + 2 < nch) {
            load_chunk((i + 2) % STAGES, (i + 2) * 32);
            CP_COMMIT();
        }
        // wait until chunk i has landed
        if (i + 2 < nch)      CP_WAIT2();
        else if (i + 1 < nch) CP_WAIT1();
        else                  CP_WAIT0();
        __syncthreads();

        const int s = i % STAGES;
        const uint32_t Ab = TILE(s, 0);
        const uint32_t Bb = TILE(s, 1);

#pragma unroll
        for (int ks = 0; ks < 2; ks++) {
            const int koff = ks * 32;
            uint32_t bh[8];
#pragma unroll
            for (int j = 0; j < 2; j++) {
                uint32_t boff = (uint32_t)((n0w + j * 16 + (b_q >> 1) * 8 + b_r) * ROWB
                                           + koff + (b_q & 1) * 16);
                LDSM_X4(bh[j*4+0], bh[j*4+1], bh[j*4+2], bh[j*4+3], Bb + boff);
            }
#pragma unroll
            for (int mi = 0; mi < 4; mi++) {
                uint32_t aoff = (uint32_t)((m0w + mi * 16 + a_r) * ROWB + koff + a_h * 16);
                uint32_t ahr[4];
                LDSM_X4(ahr[0], ahr[1], ahr[2], ahr[3], Ab + aoff);
#pragma unroll
                for (int ni = 0; ni < 4; ni++)
                    mma_h(acc[mi][ni], ahr, bh[ni*2], bh[ni*2+1]);
            }
        }
        __syncthreads();
    }

    // ---- epilogue ----
    const float* auxp = aux;
    if (HAS_RES) auxp += z * sAux;
    const int crow = lane >> 2;
    const int ccol = (lane & 3) * 2;
#pragma unroll
    for (int mi = 0; mi < 4; mi++) {
#pragma unroll
        for (int rh = 0; rh < 2; rh++) {
            const long row = m0 + m0w + mi * 16 + crow + rh * 8;
#pragma unroll
            for (int ni = 0; ni < 4; ni++) {
                const int col = n0 + n0w + ni * 8 + ccol;
                float v0 = acc[mi][ni][rh * 2];
                float v1 = acc[mi][ni][rh * 2 + 1];
                if (HAS_BIAS)  { v0 += aux[col]; v1 += aux[col + 1]; }
                if (HAS_SCALE) { v0 *= scale; v1 *= scale; }
                if (HAS_RES)   {
                    v0 += auxp[row * (long)N + col];
                    v1 += auxp[row * (long)N + col + 1];
                }
                if (WR_F32)
                    *reinterpret_cast<float2*>(Cf + cOff + row * (long)N + col) =
                        make_float2(v0, v1);
                if (WR_F16)
                    *reinterpret_cast<uint32_t*>(Ch + cOff + row * (long)N + col) =
                        pk(h16(v0), h16(v1));
            }
        }
    }
    #undef TILE
}

// ---------------------------------------------------------------------------
// In-place fp32 row softmax over 2048 columns + fp16 copy for the A*V GEMM.
// ---------------------------------------------------------------------------
__global__ void __launch_bounds__(256)
softmax_rows(float* __restrict__ att, uint16_t* __restrict__ attH)
{
    const long row = blockIdx.x;
    float* p = att + row * (long)SKV;
    uint16_t* ph = attH + row * (long)SKV;
    const int t = threadIdx.x;
    const int w = t >> 5, ln = t & 31;
    __shared__ float red[8];

    float v[8];
    float m = -INFINITY;
#pragma unroll
    for (int i = 0; i < 8; i++) {
        v[i] = p[t + i * 256];
        m = fmaxf(m, v[i]);
    }
#pragma unroll
    for (int s = 16; s > 0; s >>= 1)
        m = fmaxf(m, __shfl_xor_sync(0xFFFFFFFFu, m, s));
    if (ln == 0) red[w] = m;
    __syncthreads();
    m = red[ln & 7];
#pragma unroll
    for (int s = 4; s > 0; s >>= 1)
        m = fmaxf(m, __shfl_xor_sync(0xFFFFFFFFu, m, s));

    float sum = 0.0f;
#pragma unroll
    for (int i = 0; i < 8; i++) {
        v[i] = __expf(v[i] - m);
        sum += v[i];
    }
#pragma unroll
    for (int s = 16; s > 0; s >>= 1)
        sum += __shfl_xor_sync(0xFFFFFFFFu, sum, s);
    __syncthreads();
    if (ln == 0) red[w] = sum;
    __syncthreads();
    sum = red[ln & 7];
#pragma unroll
    for (int s = 4; s > 0; s >>= 1)
        sum += __shfl_xor_sync(0xFFFFFFFFu, sum, s);

    const float inv = 1.0f / sum;
#pragma unroll
    for (int i = 0; i < 8; i++) {
        float val = v[i] * inv;
        p[t + i * 256] = val;
        ph[t + i * 256] = h16(val);
    }
}

// ---------------------------------------------------------------------------
extern "C" void kernel_launch(void* const* d_in, const int* in_sizes, int n_in,
                              void* d_out, int out_size)
{
    const float* x  = (const float*)d_in[0];
    const float* en = (const float*)d_in[1];
    const float* Wq = (const float*)d_in[2];
    const float* bq = (const float*)d_in[3];
    const float* Wf = (const float*)d_in[4];
    const float* bf = (const float*)d_in[5];

    float* out  = (float*)d_out;
    float* proj = out;
    float* att  = out + PROJ_ELEMS;

    auto sym = [](const void* s) {
        void* p = nullptr;
        cudaGetSymbolAddress(&p, s);
        return p;
    };
    uint16_t* xh   = (uint16_t*)sym(g_xh);
    uint16_t* wqT  = (uint16_t*)sym(g_wqT);
    uint16_t* enS  = (uint16_t*)sym(g_enS);
    uint16_t* enT  = (uint16_t*)sym(g_enT);
    uint16_t* wfT  = (uint16_t*)sym(g_wfT);
    float*    qf   = (float*)   sym(g_q);
    uint16_t* qh   = (uint16_t*)sym(g_qh);
    uint16_t* attH = (uint16_t*)sym(g_attH);
    uint16_t* sumh = (uint16_t*)sym(g_sumh);

    cudaFuncSetAttribute(mma_gemm<25>, cudaFuncAttributeMaxDynamicSharedMemorySize, SMEM_BYTES);
    cudaFuncSetAttribute(mma_gemm<10>, cudaFuncAttributeMaxDynamicSharedMemorySize, SMEM_BYTES);
    cudaFuncSetAttribute(mma_gemm<20>, cudaFuncAttributeMaxDynamicSharedMemorySize, SMEM_BYTES);
    cudaFuncSetAttribute(mma_gemm<9>,  cudaFuncAttributeMaxDynamicSharedMemorySize, SMEM_BYTES);

    const float scale = 0.044194173824159216f;  // 1/sqrt(512)

    // --- pre-passes ---
    {
        long n4 = (long)BATCH * SQ * DIN / 4;
        conv_plain_f16<<<(unsigned)((n4 + 255) / 256), 256>>>(x, xh, n4);
    }
    conv_en_fused<<<dim3(DEMB / 32, SKV / 32, BATCH), dim3(32, 8)>>>(en, enS, enT);
    conv_T_f16<<<dim3(DEMB / 32, DIN / 32, 1), dim3(32, 8)>>>(Wq, wqT, DIN, DEMB);
    conv_T_f16<<<dim3(DOUT / 32, DEMB / 32, 1), dim3(32, 8)>>>(Wf, wfT, DEMB, DOUT);

    // 1) q = x @ wqT^T + bq    writes q fp32 + fp16 single. MODE=1|8|16=25
    mma_gemm<25><<<dim3(DEMB / 128, (BATCH * SQ) / 128, 1), 256, SMEM_BYTES>>>(
        xh, wqT, qf, qh, bq,
        BATCH * SQ, DEMB, DIN, 0, 0, 0, 0, 0.0f);

    // 2) scores = q @ enS^T * scale    fp32 att. MODE=2|8=10
    mma_gemm<10><<<dim3(SKV / 128, SQ / 128, BATCH), 256, SMEM_BYTES>>>(
        qh, enS, att, nullptr, nullptr,
        SQ, SKV, DEMB,
        (long)SQ * DEMB, (long)SKV * DEMB, (long)SQ * SKV, 0, scale);

    // 3) softmax in-place fp32 + fp16 copy
    softmax_rows<<<BATCH * SQ, 256>>>(att, attH);

    // 4) sum = attH @ enT^T + q    fp16 sum out. MODE=4|16=20
    mma_gemm<20><<<dim3(DEMB / 128, SQ / 128, BATCH), 256, SMEM_BYTES>>>(
        attH, enT, nullptr, sumh, qf,
        SQ, DEMB, SKV,
        (long)SQ * SKV, (long)DEMB * SKV, (long)SQ * DEMB, (long)SQ * DEMB, 0.0f);

    // 5) proj = sumh @ wfT^T + bf    fp32 out. MODE=1|8=9
    mma_gemm<9><<<dim3(DOUT / 128, (BATCH * SQ) / 128, 1), 256, SMEM_BYTES>>>(
        sumh, wfT, proj, nullptr, bf,
        BATCH * SQ, DOUT, DEMB, 0, 0, 0, 0, 0.0f);

    (void)in_sizes; (void)n_in; (void)out_size;
}

// round 16
// speedup vs baseline: 6.1355x; 1.1666x over previous
#include <cuda_runtime.h>
#include <cuda_fp16.h>
#include <math.h>
#include <stdint.h>

// ---------------------------------------------------------------------------
// Problem constants
// ---------------------------------------------------------------------------
constexpr int BATCH = 8;
constexpr int SQ    = 2048;
constexpr int SKV   = 2048;
constexpr int DIN   = 1024;
constexpr int DEMB  = 512;
constexpr int DOUT  = 512;

constexpr long PROJ_ELEMS = (long)BATCH * SQ * DOUT;

// ---------------------------------------------------------------------------
// Scratch (device globals; no allocation allowed)
// ---------------------------------------------------------------------------
__device__ __align__(16) uint16_t g_xh  [(long)BATCH * SQ * DIN];    // fp16
__device__ __align__(16) uint16_t g_wqT [DEMB * DIN];                // fp16
__device__ __align__(16) uint16_t g_enS [(long)BATCH * SKV * DEMB];  // fp16, K-major
__device__ __align__(16) uint16_t g_enT [(long)BATCH * DEMB * SKV];  // fp16, transposed
__device__ __align__(16) uint16_t g_wfT [DOUT * DEMB];               // fp16
__device__ __align__(16) float    g_q   [(long)BATCH * SQ * DEMB];   // fp32 (residual)
__device__ __align__(16) uint16_t g_qh  [(long)BATCH * SQ * DEMB];   // fp16 single
__device__ __align__(16) uint16_t g_attH[(long)BATCH * SQ * SKV];    // fp16 att (post-softmax)
__device__ __align__(16) uint16_t g_sumh[(long)BATCH * SQ * DEMB];   // fp16 sum

// ---------------------------------------------------------------------------
// PTX helpers (sm_80-compatible path: mma.sync / ldmatrix / cp.async)
// ---------------------------------------------------------------------------
__device__ __forceinline__ uint32_t smem_u32(const void* p) {
    uint32_t a;
    asm("{ .reg .u64 t; cvta.to.shared.u64 t, %1; cvt.u32.u64 %0, t; }" : "=r"(a) : "l"(p));
    return a;
}

#define CP_ASYNC16(dst, src) \
    asm volatile("cp.async.cg.shared.global [%0], [%1], 16;" :: "r"(dst), "l"(src))
#define CP_COMMIT()  asm volatile("cp.async.commit_group;" ::: "memory")
#define CP_WAIT0()   asm volatile("cp.async.wait_group 0;" ::: "memory")
#define CP_WAIT1()   asm volatile("cp.async.wait_group 1;" ::: "memory")
#define CP_WAIT2()   asm volatile("cp.async.wait_group 2;" ::: "memory")

#define LDSM_X4(r0, r1, r2, r3, addr) \
    asm volatile("ldmatrix.sync.aligned.m8n8.x4.shared.b16 {%0,%1,%2,%3}, [%4];" \
                 : "=r"(r0), "=r"(r1), "=r"(r2), "=r"(r3) : "r"(addr))

__device__ __forceinline__ void mma_h(float* d, const uint32_t* a, uint32_t b0, uint32_t b1) {
    asm volatile("mma.sync.aligned.m16n8k16.row.col.f32.f16.f16.f32 "
                 "{%0,%1,%2,%3}, {%4,%5,%6,%7}, {%8,%9}, {%0,%1,%2,%3};"
                 : "+f"(d[0]), "+f"(d[1]), "+f"(d[2]), "+f"(d[3])
                 : "r"(a[0]), "r"(a[1]), "r"(a[2]), "r"(a[3]), "r"(b0), "r"(b1));
}

// ---------------------------------------------------------------------------
// helpers
// ---------------------------------------------------------------------------
__device__ __forceinline__ uint32_t pk(uint16_t a, uint16_t b) {
    return (uint32_t)a | ((uint32_t)b << 16);
}
__device__ __forceinline__ uint16_t h16(float v) {
    return __half_as_ushort(__float2half_rn(v));
}

// ---------------------------------------------------------------------------
// Pre-pass kernels
// ---------------------------------------------------------------------------
// plain fp32 -> fp16 convert
__global__ void __launch_bounds__(256)
conv_plain_f16(const float* __restrict__ src, uint16_t* __restrict__ dst, long n4)
{
    long i = (long)blockIdx.x * 256 + threadIdx.x;
    if (i >= n4) return;
    float4 v = reinterpret_cast<const float4*>(src)[i];
    reinterpret_cast<uint2*>(dst)[i] =
        make_uint2(pk(h16(v.x), h16(v.y)), pk(h16(v.z), h16(v.w)));
}

// en -> fp16 single (same layout) + fp16 single transposed [DEMB, SKV]
__global__ void __launch_bounds__(256)
conv_en_fused(const float* __restrict__ en, uint16_t* __restrict__ eS,
              uint16_t* __restrict__ eT)
{
    const long z = blockIdx.z;
    en += z * (long)SKV * DEMB;
    eS += z * (long)SKV * DEMB;
    eT += z * (long)DEMB * SKV;
    __shared__ float t[32][33];
    const int c0 = blockIdx.x * 32;   // DEMB
    const int r0 = blockIdx.y * 32;   // SKV
    const int tx = threadIdx.x, ty = threadIdx.y;
#pragma unroll
    for (int j = 0; j < 4; j++) {
        int r = r0 + ty + j * 8;
        float v = en[(long)r * DEMB + c0 + tx];
        t[ty + j * 8][tx] = v;
        eS[(long)r * DEMB + c0 + tx] = h16(v);
    }
    __syncthreads();
#pragma unroll
    for (int j = 0; j < 4; j++) {
        int c = c0 + ty + j * 8;
        eT[(long)c * SKV + r0 + tx] = h16(t[tx][ty + j * 8]);
    }
}

// W [R,C] fp32 -> WT [C,R] fp16 single
__global__ void __launch_bounds__(256)
conv_T_f16(const float* __restrict__ src, uint16_t* __restrict__ dstT, int R, int C)
{
    __shared__ float t[32][33];
    const int c0 = blockIdx.x * 32;
    const int r0 = blockIdx.y * 32;
    const int tx = threadIdx.x, ty = threadIdx.y;
#pragma unroll
    for (int j = 0; j < 4; j++) {
        int r = r0 + ty + j * 8;
        t[ty + j * 8][tx] = src[(long)r * C + c0 + tx];
    }
    __syncthreads();
#pragma unroll
    for (int j = 0; j < 4; j++) {
        int c = c0 + ty + j * 8;
        dstT[(long)c * R + r0 + tx] = h16(t[tx][ty + j * 8]);
    }
}

// ---------------------------------------------------------------------------
// fp16 HMMA GEMM: C[M,N] = A[M,K] @ B[N,K]^T (+epilogue)
// 1-pass fp16, 3-stage cp.async pipeline, 2 SMEM tiles per stage,
// 4 warps of 64x64 (CTA tile 128x128), mma.sync m16n8k16.
// MODE bits: 1=bias, 2=scale, 4=residual, 8=write fp32, 16=write fp16 single
// ---------------------------------------------------------------------------
constexpr int ROWB  = 80;             // padded row bytes (32 elems * 2B = 64B data)
constexpr int TILEB = 128 * ROWB;     // 10240 B
constexpr int STAGES = 3;
constexpr int SMEM_BYTES = STAGES * 2 * TILEB;  // 61440
constexpr int GTHREADS = 128;         // 4 warps

template <int MODE>
__global__ void __launch_bounds__(GTHREADS, 2)
mma_gemm(const uint16_t* __restrict__ Ah, const uint16_t* __restrict__ Bs,
         float* __restrict__ Cf, uint16_t* __restrict__ Ch,
         const float* __restrict__ aux,
         int M, int N, int K, long sA, long sB, long sC, long sAux, float scale)
{
    constexpr bool HAS_BIAS  = (MODE & 1)  != 0;
    constexpr bool HAS_SCALE = (MODE & 2)  != 0;
    constexpr bool HAS_RES   = (MODE & 4)  != 0;
    constexpr bool WR_F32    = (MODE & 8)  != 0;
    constexpr bool WR_F16    = (MODE & 16) != 0;

    extern __shared__ __align__(128) char dsm[];
    const uint32_t sbase = smem_u32(dsm);
    #define TILE(s, t) (sbase + ((s) * 2 + (t)) * TILEB)

    const int tid  = threadIdx.x;
    const int wid  = tid >> 5;
    const int lane = tid & 31;

    const long z = blockIdx.z;
    Ah += z * sA;
    Bs += z * sB;
    const long cOff = z * sC;

    const int m0 = blockIdx.y * 128;
    const int n0 = blockIdx.x * 128;

    const int lrow = tid >> 2;           // 0..31
    const int lkg  = tid & 3;            // 16B group
    auto load_chunk = [&](int s, int k0) {
        {
            const uint16_t* g = Ah + (long)m0 * K + k0;
            const uint32_t st = TILE(s, 0);
#pragma unroll
            for (int h = 0; h < 4; h++) {
                int row = lrow + h * 32;
                CP_ASYNC16(st + row * ROWB + lkg * 16, g + (long)row * K + lkg * 8);
            }
        }
        {
            const uint16_t* g = Bs + (long)n0 * K + k0;
            const uint32_t st = TILE(s, 1);
#pragma unroll
            for (int h = 0; h < 4; h++) {
                int row = lrow + h * 32;
                CP_ASYNC16(st + row * ROWB + lkg * 16, g + (long)row * K + lkg * 8);
            }
        }
    };

    float acc[4][8][4];
#pragma unroll
    for (int a = 0; a < 4; a++)
#pragma unroll
        for (int b = 0; b < 8; b++)
#pragma unroll
            for (int c = 0; c < 4; c++) acc[a][b][c] = 0.0f;

    const int nch = K >> 5;

    // prologue: 2 chunk-loads in flight
    load_chunk(0, 0);
    CP_COMMIT();
    if (nch > 1) {
        load_chunk(1, 32);
        CP_COMMIT();
    }

    // warp layout: 2 (m) x 2 (n); warp tile 64x64
    const int m0w = (wid & 1) * 64;
    const int n0w = (wid >> 1) * 64;
    const int a_r = lane & 15;
    const int a_h = lane >> 4;
    const int b_r = lane & 7;
    const int b_q = lane >> 3;

    for (int i = 0; i < nch; i++) {
        // issue load for chunk i+2 (stage reuse protected by the trailing
        // __syncthreads of iteration i-1)
        if (i + 2 < nch) {
            load_chunk((i + 2) % STAGES, (i + 2) * 32);
            CP_COMMIT();
        }
        // wait until chunk i has landed
        if (i + 2 < nch)      CP_WAIT2();
        else if (i + 1 < nch) CP_WAIT1();
        else                  CP_WAIT0();
        __syncthreads();

        const int s = i % STAGES;
        const uint32_t Ab = TILE(s, 0);
        const uint32_t Bb = TILE(s, 1);

#pragma unroll
        for (int ks = 0; ks < 2; ks++) {
            const int koff = ks * 32;
            uint32_t bh[16];
#pragma unroll
            for (int j = 0; j < 4; j++) {
                uint32_t boff = (uint32_t)((n0w + j * 16 + (b_q >> 1) * 8 + b_r) * ROWB
                                           + koff + (b_q & 1) * 16);
                LDSM_X4(bh[j*4+0], bh[j*4+1], bh[j*4+2], bh[j*4+3], Bb + boff);
            }
#pragma unroll
            for (int mi = 0; mi < 4; mi++) {
                uint32_t aoff = (uint32_t)((m0w + mi * 16 + a_r) * ROWB + koff + a_h * 16);
                uint32_t ahr[4];
                LDSM_X4(ahr[0], ahr[1], ahr[2], ahr[3], Ab + aoff);
#pragma unroll
                for (int ni = 0; ni < 8; ni++)
                    mma_h(acc[mi][ni], ahr, bh[ni*2], bh[ni*2+1]);
            }
        }
        __syncthreads();
    }

    // ---- epilogue ----
    const float* auxp = aux;
    if (HAS_RES) auxp += z * sAux;
    const int crow = lane >> 2;
    const int ccol = (lane & 3) * 2;
#pragma unroll
    for (int mi = 0; mi < 4; mi++) {
#pragma unroll
        for (int rh = 0; rh < 2; rh++) {
            const long row = m0 + m0w + mi * 16 + crow + rh * 8;
#pragma unroll
            for (int ni = 0; ni < 8; ni++) {
                const int col = n0 + n0w + ni * 8 + ccol;
                float v0 = acc[mi][ni][rh * 2];
                float v1 = acc[mi][ni][rh * 2 + 1];
                if (HAS_BIAS)  { v0 += aux[col]; v1 += aux[col + 1]; }
                if (HAS_SCALE) { v0 *= scale; v1 *= scale; }
                if (HAS_RES)   {
                    v0 += auxp[row * (long)N + col];
                    v1 += auxp[row * (long)N + col + 1];
                }
                if (WR_F32)
                    *reinterpret_cast<float2*>(Cf + cOff + row * (long)N + col) =
                        make_float2(v0, v1);
                if (WR_F16)
                    *reinterpret_cast<uint32_t*>(Ch + cOff + row * (long)N + col) =
                        pk(h16(v0), h16(v1));
            }
        }
    }
    #undef TILE
}

// ---------------------------------------------------------------------------
// In-place fp32 row softmax over 2048 columns + fp16 copy for the A*V GEMM.
// ---------------------------------------------------------------------------
__global__ void __launch_bounds__(256)
softmax_rows(float* __restrict__ att, uint16_t* __restrict__ attH)
{
    const long row = blockIdx.x;
    float* p = att + row * (long)SKV;
    uint16_t* ph = attH + row * (long)SKV;
    const int t = threadIdx.x;
    const int w = t >> 5, ln = t & 31;
    __shared__ float red[8];

    float v[8];
    float m = -INFINITY;
#pragma unroll
    for (int i = 0; i < 8; i++) {
        v[i] = p[t + i * 256];
        m = fmaxf(m, v[i]);
    }
#pragma unroll
    for (int s = 16; s > 0; s >>= 1)
        m = fmaxf(m, __shfl_xor_sync(0xFFFFFFFFu, m, s));
    if (ln == 0) red[w] = m;
    __syncthreads();
    m = red[ln & 7];
#pragma unroll
    for (int s = 4; s > 0; s >>= 1)
        m = fmaxf(m, __shfl_xor_sync(0xFFFFFFFFu, m, s));

    float sum = 0.0f;
#pragma unroll
    for (int i = 0; i < 8; i++) {
        v[i] = __expf(v[i] - m);
        sum += v[i];
    }
#pragma unroll
    for (int s = 16; s > 0; s >>= 1)
        sum += __shfl_xor_sync(0xFFFFFFFFu, sum, s);
    __syncthreads();
    if (ln == 0) red[w] = sum;
    __syncthreads();
    sum = red[ln & 7];
#pragma unroll
    for (int s = 4; s > 0; s >>= 1)
        sum += __shfl_xor_sync(0xFFFFFFFFu, sum, s);

    const float inv = 1.0f / sum;
#pragma unroll
    for (int i = 0; i < 8; i++) {
        float val = v[i] * inv;
        p[t + i * 256] = val;
        ph[t + i * 256] = h16(val);
    }
}

// ---------------------------------------------------------------------------
extern "C" void kernel_launch(void* const* d_in, const int* in_sizes, int n_in,
                              void* d_out, int out_size)
{
    const float* x  = (const float*)d_in[0];
    const float* en = (const float*)d_in[1];
    const float* Wq = (const float*)d_in[2];
    const float* bq = (const float*)d_in[3];
    const float* Wf = (const float*)d_in[4];
    const float* bf = (const float*)d_in[5];

    float* out  = (float*)d_out;
    float* proj = out;
    float* att  = out + PROJ_ELEMS;

    auto sym = [](const void* s) {
        void* p = nullptr;
        cudaGetSymbolAddress(&p, s);
        return p;
    };
    uint16_t* xh   = (uint16_t*)sym(g_xh);
    uint16_t* wqT  = (uint16_t*)sym(g_wqT);
    uint16_t* enS  = (uint16_t*)sym(g_enS);
    uint16_t* enT  = (uint16_t*)sym(g_enT);
    uint16_t* wfT  = (uint16_t*)sym(g_wfT);
    float*    qf   = (float*)   sym(g_q);
    uint16_t* qh   = (uint16_t*)sym(g_qh);
    uint16_t* attH = (uint16_t*)sym(g_attH);
    uint16_t* sumh = (uint16_t*)sym(g_sumh);

    cudaFuncSetAttribute(mma_gemm<25>, cudaFuncAttributeMaxDynamicSharedMemorySize, SMEM_BYTES);
    cudaFuncSetAttribute(mma_gemm<10>, cudaFuncAttributeMaxDynamicSharedMemorySize, SMEM_BYTES);
    cudaFuncSetAttribute(mma_gemm<20>, cudaFuncAttributeMaxDynamicSharedMemorySize, SMEM_BYTES);
    cudaFuncSetAttribute(mma_gemm<9>,  cudaFuncAttributeMaxDynamicSharedMemorySize, SMEM_BYTES);

    const float scale = 0.044194173824159216f;  // 1/sqrt(512)

    // --- pre-passes ---
    {
        long n4 = (long)BATCH * SQ * DIN / 4;
        conv_plain_f16<<<(unsigned)((n4 + 255) / 256), 256>>>(x, xh, n4);
    }
    conv_en_fused<<<dim3(DEMB / 32, SKV / 32, BATCH), dim3(32, 8)>>>(en, enS, enT);
    conv_T_f16<<<dim3(DEMB / 32, DIN / 32, 1), dim3(32, 8)>>>(Wq, wqT, DIN, DEMB);
    conv_T_f16<<<dim3(DOUT / 32, DEMB / 32, 1), dim3(32, 8)>>>(Wf, wfT, DEMB, DOUT);

    // 1) q = x @ wqT^T + bq    writes q fp32 + fp16 single. MODE=1|8|16=25
    mma_gemm<25><<<dim3(DEMB / 128, (BATCH * SQ) / 128, 1), GTHREADS, SMEM_BYTES>>>(
        xh, wqT, qf, qh, bq,
        BATCH * SQ, DEMB, DIN, 0, 0, 0, 0, 0.0f);

    // 2) scores = q @ enS^T * scale    fp32 att. MODE=2|8=10
    mma_gemm<10><<<dim3(SKV / 128, SQ / 128, BATCH), GTHREADS, SMEM_BYTES>>>(
        qh, enS, att, nullptr, nullptr,
        SQ, SKV, DEMB,
        (long)SQ * DEMB, (long)SKV * DEMB, (long)SQ * SKV, 0, scale);

    // 3) softmax in-place fp32 + fp16 copy
    softmax_rows<<<BATCH * SQ, 256>>>(att, attH);

    // 4) sum = attH @ enT^T + q    fp16 sum out. MODE=4|16=20
    mma_gemm<20><<<dim3(DEMB / 128, SQ / 128, BATCH), GTHREADS, SMEM_BYTES>>>(
        attH, enT, nullptr, sumh, qf,
        SQ, DEMB, SKV,
        (long)SQ * SKV, (long)DEMB * SKV, (long)SQ * DEMB, (long)SQ * DEMB, 0.0f);

    // 5) proj = sumh @ wfT^T + bf    fp32 out. MODE=1|8=9
    mma_gemm<9><<<dim3(DOUT / 128, (BATCH * SQ) / 128, 1), GTHREADS, SMEM_BYTES>>>(
        sumh, wfT, proj, nullptr, bf,
        BATCH * SQ, DOUT, DEMB, 0, 0, 0, 0, 0.0f);

    (void)in_sizes; (void)n_in; (void)out_size;
}